// round 2
// baseline (speedup 1.0000x reference)
#include <cuda_runtime.h>

#define N_NODES 20000
#define N_EDGES 160000
#define NH 8
#define EPS 1e-12f
#define SLOPE 0.2f

// ---------------- scratch ----------------
__device__ float g_value[N_NODES * 256];
__device__ float g_scal[N_NODES * 32];   // 0-7 ssrc | 8-15 stgt | 16-23 gate1 | 24-31 q
__device__ float g_B2[256 * 32];         // composed scalar-projection matrix
__device__ float g_cq[NH];               // nbias . gate_w[256:]
__device__ float g_srel_dr[50 * NH];
__device__ float g_srel_da[4 * NH];
__device__ int g_deg[N_NODES];
__device__ int g_cursor[N_NODES];
__device__ int g_off[N_NODES + 1];
__device__ int g_esort[N_EDGES];
__device__ unsigned g_maxraw[2];

__device__ __forceinline__ float leaky(float x) { return x >= 0.f ? x : SLOPE * x; }

__device__ __forceinline__ unsigned encodef(float f) {
    unsigned b = __float_as_uint(f);
    return (b & 0x80000000u) ? ~b : (b | 0x80000000u);
}
__device__ __forceinline__ float decodef(unsigned u) {
    unsigned b = (u & 0x80000000u) ? (u & 0x7FFFFFFFu) : ~u;
    return __uint_as_float(b);
}

// ---------------- init ----------------
__global__ void k_init() {
    int i = blockIdx.x * blockDim.x + threadIdx.x;
    if (i < N_NODES) { g_deg[i] = 0; g_cursor[i] = 0; }
    if (i < 2) g_maxraw[i] = 0u;
}

// ---------------- relation score tables ----------------
__global__ void k_tables(const float* __restrict__ Wrel, const float* __restrict__ wrel,
                         const float* __restrict__ dre_emb, const float* __restrict__ dae_emb) {
    __shared__ float us[NH * 128];
    int tid = threadIdx.x;
    for (int id = tid; id < NH * 128; id += 256) {
        int h = id >> 7, k = id & 127;
        float s = 0.f;
#pragma unroll
        for (int j = 0; j < 16; j++) s += Wrel[k * 128 + h * 16 + j] * wrel[h * 16 + j];
        us[h * 128 + k] = s;
    }
    __syncthreads();
    for (int id = tid; id < 50 * NH; id += 256) {
        int r = id / NH, h = id % NH;
        float s = 0.f;
        for (int k = 0; k < 64; k++) s += dre_emb[r * 64 + k] * us[h * 128 + k];
        g_srel_dr[r * NH + h] = s;
    }
    for (int id = tid; id < 4 * NH; id += 256) {
        int a = id / NH, h = id % NH;
        float s = 0.f;
        for (int k = 0; k < 64; k++) s += dae_emb[a * 64 + k] * us[h * 128 + 64 + k];
        g_srel_da[a * NH + h] = s;
    }
}

// ---------------- compose the scalar projection matrix B2 [256 x 32] ----------------
__global__ void k_prep(const float* __restrict__ Wv, const float* __restrict__ wsrc,
                       const float* __restrict__ wtgt, const float* __restrict__ gatew,
                       const float* __restrict__ Wn, const float* __restrict__ nbias) {
    int k = threadIdx.x;  // 256 threads, one per input dim
#pragma unroll
    for (int h = 0; h < NH; h++) {
        float s1 = 0.f, s2 = 0.f;
#pragma unroll
        for (int d = 0; d < 32; d++) {
            float v = Wv[k * 256 + h * 32 + d];
            s1 += v * wsrc[h * 32 + d];
            s2 += v * wtgt[h * 32 + d];
        }
        g_B2[k * 32 + h] = s1;
        g_B2[k * 32 + 8 + h] = s2;
        g_B2[k * 32 + 16 + h] = gatew[k * 8 + h];
        float s3 = 0.f;
        for (int t = 0; t < 256; t++) s3 += Wn[k * 256 + t] * gatew[(256 + t) * 8 + h];
        g_B2[k * 32 + 24 + h] = s3;
    }
    if (k < NH) {
        float c = 0.f;
        for (int t = 0; t < 256; t++) c += nbias[t] * gatew[(256 + t) * 8 + k];
        g_cq[k] = c;
    }
}

// ---------------- CSR count + scan ----------------
__global__ void k_count(const int* __restrict__ ei) {
    int e = blockIdx.x * blockDim.x + threadIdx.x;
    if (e < N_EDGES) atomicAdd(&g_deg[ei[N_EDGES + e]], 1);
}

__global__ void k_scan() {  // 1 block, 1024 threads, warp-shuffle scan
    __shared__ int wsums[32];
    __shared__ int carry_s;
    int tid = threadIdx.x, lane = tid & 31, wid = tid >> 5;
    if (tid == 0) carry_s = 0;
    __syncthreads();
    for (int base = 0; base < N_NODES; base += 1024) {
        int i = base + tid;
        int v = (i < N_NODES) ? g_deg[i] : 0;
        int x = v;
#pragma unroll
        for (int o = 1; o < 32; o <<= 1) {
            int t = __shfl_up_sync(0xFFFFFFFFu, x, o);
            if (lane >= o) x += t;
        }
        if (lane == 31) wsums[wid] = x;
        __syncthreads();
        if (wid == 0) {
            int s = wsums[lane];
#pragma unroll
            for (int o = 1; o < 32; o <<= 1) {
                int t = __shfl_up_sync(0xFFFFFFFFu, s, o);
                if (lane >= o) s += t;
            }
            wsums[lane] = s;
        }
        __syncthreads();
        int wpre = wid ? wsums[wid - 1] : 0;
        int carry = carry_s;
        if (i < N_NODES) g_off[i] = carry + wpre + x - v;
        int tot = wsums[31];
        __syncthreads();
        if (tid == 0) carry_s = carry + tot;
        __syncthreads();
    }
    if (threadIdx.x == 0) g_off[N_NODES] = carry_s;
}

// ---------------- fused GEMM: [N,256] @ [256, 256|32] -> value | scal ----------------
#define BM 128
#define BN 64
#define BK 16
#define ASTR 132
#define BSTR 68

__global__ void __launch_bounds__(256) k_gemm(const float* __restrict__ inp,
                                              const float* __restrict__ Wv) {
    __shared__ float As[2][BK][ASTR];
    __shared__ float Bs[2][BK][BSTR];
    int tid = threadIdx.x;
    int bx = blockIdx.x, by = blockIdx.y;
    int row0 = by * BM;
    bool scal = (bx == 4);
    int col0 = bx * BN;

    int am = tid >> 2, ak = (tid & 3) << 2;   // A: 2 rows/thread (am, am+64), 4 k each
    int bk = tid >> 4, bc = (tid & 15) << 2;  // B: 1 float4/thread
    int tx = tid & 15, ty = tid >> 4;

    float acc[8][4];
#pragma unroll
    for (int i = 0; i < 8; i++)
#pragma unroll
        for (int j = 0; j < 4; j++) acc[i][j] = 0.f;

    int r0i = row0 + am, r1i = row0 + am + 64;
    bool v0 = r0i < N_NODES, v1 = r1i < N_NODES;
    float4 ra0, ra1, rb;
    const float4 z4 = make_float4(0.f, 0.f, 0.f, 0.f);

    // prologue load k0=0
    ra0 = v0 ? *(const float4*)(inp + (size_t)r0i * 256 + ak) : z4;
    ra1 = v1 ? *(const float4*)(inp + (size_t)r1i * 256 + ak) : z4;
    if (!scal) rb = *(const float4*)(Wv + (size_t)bk * 256 + col0 + bc);
    else rb = (bc < 32) ? *(const float4*)(g_B2 + bk * 32 + bc) : z4;

    As[0][ak + 0][am] = ra0.x; As[0][ak + 1][am] = ra0.y;
    As[0][ak + 2][am] = ra0.z; As[0][ak + 3][am] = ra0.w;
    As[0][ak + 0][am + 64] = ra1.x; As[0][ak + 1][am + 64] = ra1.y;
    As[0][ak + 2][am + 64] = ra1.z; As[0][ak + 3][am + 64] = ra1.w;
    *(float4*)&Bs[0][bk][bc] = rb;
    __syncthreads();

    for (int t = 0; t < 16; t++) {
        int buf = t & 1;
        if (t < 15) {
            int k0 = (t + 1) * BK;
            ra0 = v0 ? *(const float4*)(inp + (size_t)r0i * 256 + k0 + ak) : z4;
            ra1 = v1 ? *(const float4*)(inp + (size_t)r1i * 256 + k0 + ak) : z4;
            if (!scal) rb = *(const float4*)(Wv + (size_t)(k0 + bk) * 256 + col0 + bc);
            else rb = (bc < 32) ? *(const float4*)(g_B2 + (k0 + bk) * 32 + bc) : z4;
        }
#pragma unroll
        for (int kk = 0; kk < BK; kk++) {
            float4 a0 = *(const float4*)&As[buf][kk][ty * 8];
            float4 a1 = *(const float4*)&As[buf][kk][ty * 8 + 4];
            float4 b4 = *(const float4*)&Bs[buf][kk][tx * 4];
            float a[8] = {a0.x, a0.y, a0.z, a0.w, a1.x, a1.y, a1.z, a1.w};
            float b[4] = {b4.x, b4.y, b4.z, b4.w};
#pragma unroll
            for (int i = 0; i < 8; i++)
#pragma unroll
                for (int j = 0; j < 4; j++) acc[i][j] += a[i] * b[j];
        }
        if (t < 15) {
            int nb = buf ^ 1;
            As[nb][ak + 0][am] = ra0.x; As[nb][ak + 1][am] = ra0.y;
            As[nb][ak + 2][am] = ra0.z; As[nb][ak + 3][am] = ra0.w;
            As[nb][ak + 0][am + 64] = ra1.x; As[nb][ak + 1][am + 64] = ra1.y;
            As[nb][ak + 2][am + 64] = ra1.z; As[nb][ak + 3][am + 64] = ra1.w;
            *(float4*)&Bs[nb][bk][bc] = rb;
            __syncthreads();
        }
    }

#pragma unroll
    for (int i = 0; i < 8; i++) {
        int r = row0 + ty * 8 + i;
        if (r >= N_NODES) continue;
        float4 o = make_float4(acc[i][0], acc[i][1], acc[i][2], acc[i][3]);
        if (!scal) {
            *(float4*)(g_value + (size_t)r * 256 + col0 + tx * 4) = o;
        } else if (tx * 4 < 32) {
            *(float4*)(g_scal + (size_t)r * 32 + tx * 4) = o;
        }
    }
}

// ---------------- CSR fill + fused global score max ----------------
__global__ void k_fillmax(const int* __restrict__ ei, const int* __restrict__ dre,
                          const int* __restrict__ dae) {
    int e = blockIdx.x * blockDim.x + threadIdx.x;
    float mv = -1e30f, mr = -1e30f;
    if (e < N_EDGES) {
        int src = ei[e], tgt = ei[N_EDGES + e], dr = dre[e], da = dae[e];
        int pos = g_off[tgt] + atomicAdd(&g_cursor[tgt], 1);
        g_esort[pos] = src | (dr << 16) | (da << 22);
#pragma unroll
        for (int h = 0; h < NH; h++) {
            float st = g_scal[tgt * 32 + 8 + h];
            float rv = g_scal[src * 32 + h] + st;
            float rr = g_srel_dr[dr * 8 + h] + g_srel_da[da * 8 + h] + st;
            mv = fmaxf(mv, rv);
            mr = fmaxf(mr, rr);
        }
    }
#pragma unroll
    for (int o = 16; o; o >>= 1) {
        mv = fmaxf(mv, __shfl_xor_sync(0xFFFFFFFFu, mv, o));
        mr = fmaxf(mr, __shfl_xor_sync(0xFFFFFFFFu, mr, o));
    }
    if ((threadIdx.x & 31) == 0) {
        atomicMax(&g_maxraw[0], encodef(mv));
        atomicMax(&g_maxraw[1], encodef(mr));
    }
}

// ---------------- aggregation + epilogue: one block per target node ----------------
__global__ void __launch_bounds__(256) k_agg(const float* __restrict__ fpw,
                                             const float* __restrict__ fpb,
                                             const float* __restrict__ gateb,
                                             const float* __restrict__ fbias,
                                             float* __restrict__ out) {
    __shared__ float tdr[50 * NH];
    __shared__ float tda[4 * NH];
    __shared__ float cat[8][64];
    int tid = threadIdx.x;
    int lane = tid & 31, h = tid >> 5;
    for (int i = tid; i < 50 * NH; i += 256) tdr[i] = g_srel_dr[i];
    if (tid < 32) tda[tid] = g_srel_da[tid];
    __syncthreads();

    int n = blockIdx.x;
    float Mv = leaky(decodef(g_maxraw[0]));
    float Mr = leaky(decodef(g_maxraw[1]));
    int e0 = g_off[n], e1 = g_off[n + 1];
    float stgt = g_scal[n * 32 + 8 + h];
    float accv = 0.f, accr = 0.f, denv = 0.f, denr = 0.f, accq = 0.f;
    for (int p = e0; p < e1; p++) {
        int pk = g_esort[p];
        int src = pk & 0xFFFF;
        int dr = (pk >> 16) & 0x3F;
        int da = (pk >> 22) & 0x3;
        float ssrc = g_scal[src * 32 + h];
        float q = g_scal[src * 32 + 24 + h];
        float rv = ssrc + stgt;
        float rr = tdr[dr * 8 + h] + tda[da * 8 + h] + stgt;
        float ev = __expf(leaky(rv) - Mv);
        float er = __expf(leaky(rr) - Mr);
        denv += ev;
        denr += er;
        accq += q;
        float x = g_value[(size_t)src * 256 + h * 32 + lane];
        accv += ev * x;
        accr += er * x;
    }
    accv /= (denv + EPS);
    accr /= (denr + EPS);

    cat[h][lane] = accv;
    cat[h][32 + lane] = accr;
    __syncthreads();

    int deg = e1 - e0;
    float nbterm = deg > 0 ? accq / (float)deg + g_cq[h] : 0.f;
    float gate = 1.f / (1.f + __expf(-(g_scal[n * 32 + 16 + h] + nbterm + gateb[h])));

    float ho = fpb[h * 32 + lane];
#pragma unroll
    for (int d = 0; d < 64; d++) ho += cat[h][d] * fpw[h * 2048 + d * 32 + lane];

    out[(size_t)n * 256 + h * 32 + lane] = ho * gate + fbias[h * 32 + lane];
}

// ---------------- launcher ----------------
extern "C" void kernel_launch(void* const* d_in, const int* in_sizes, int n_in,
                              void* d_out, int out_size) {
    const float* inp = (const float*)d_in[0];
    const float* Wv = (const float*)d_in[2];
    const float* Wrel = (const float*)d_in[3];
    const float* dre_emb = (const float*)d_in[4];
    const float* dae_emb = (const float*)d_in[5];
    const float* wsrc = (const float*)d_in[6];
    const float* wtgt = (const float*)d_in[7];
    const float* wrel = (const float*)d_in[8];
    const float* fpw = (const float*)d_in[9];
    const float* fpb = (const float*)d_in[10];
    const float* Wn = (const float*)d_in[11];
    const float* nbias = (const float*)d_in[12];
    const float* gatew = (const float*)d_in[13];
    const float* gateb = (const float*)d_in[14];
    const float* fbias = (const float*)d_in[15];
    const int* ei = (const int*)d_in[16];
    const int* dre = (const int*)d_in[17];
    const int* dae = (const int*)d_in[18];
    float* out = (float*)d_out;

    k_init<<<(N_NODES + 255) / 256, 256>>>();                       // 1
    k_tables<<<1, 256>>>(Wrel, wrel, dre_emb, dae_emb);             // 2
    k_prep<<<1, 256>>>(Wv, wsrc, wtgt, gatew, Wn, nbias);           // 3
    k_count<<<(N_EDGES + 255) / 256, 256>>>(ei);                    // 4
    k_scan<<<1, 1024>>>();                                          // 5
    k_gemm<<<dim3(5, (N_NODES + BM - 1) / BM), 256>>>(inp, Wv);     // 6 (profiled)
    k_fillmax<<<(N_EDGES + 255) / 256, 256>>>(ei, dre, dae);        // 7
    k_agg<<<N_NODES, 256>>>(fpw, fpb, gateb, fbias, out);           // 8
}

// round 3
// speedup vs baseline: 2.2171x; 2.2171x over previous
#include <cuda_runtime.h>

#define N_NODES 20000
#define N_EDGES 160000
#define NH 8
#define EPS 1e-12f
#define SLOPE 0.2f

// ---------------- scratch ----------------
__device__ float g_value[N_NODES * 256];
__device__ float g_scal[N_NODES * 32];   // 0-7 ssrc | 8-15 stgt | 16-23 gate1 | 24-31 q
__device__ float g_B2[256 * 32];         // composed scalar-projection matrix
__device__ float g_cq[NH];               // nbias . gate_w[256:]
__device__ float g_srel_dr[50 * NH];
__device__ float g_srel_da[4 * NH];
__device__ int g_deg[N_NODES];
__device__ int g_cursor[N_NODES];
__device__ int g_off[N_NODES + 1];
__device__ int g_esort[N_EDGES];
__device__ unsigned g_maxraw[2];

__device__ __forceinline__ float leaky(float x) { return x >= 0.f ? x : SLOPE * x; }

__device__ __forceinline__ float wsum(float v) {
#pragma unroll
    for (int o = 16; o; o >>= 1) v += __shfl_xor_sync(0xFFFFFFFFu, v, o);
    return v;
}

__device__ __forceinline__ unsigned encodef(float f) {
    unsigned b = __float_as_uint(f);
    return (b & 0x80000000u) ? ~b : (b | 0x80000000u);
}
__device__ __forceinline__ float decodef(unsigned u) {
    unsigned b = (u & 0x80000000u) ? (u & 0x7FFFFFFFu) : ~u;
    return __uint_as_float(b);
}

// ---------------- init ----------------
__global__ void k_init() {
    int i = blockIdx.x * blockDim.x + threadIdx.x;
    if (i < N_NODES) { g_deg[i] = 0; g_cursor[i] = 0; }
    if (i < 2) g_maxraw[i] = 0u;
}

// ---------------- relation score tables ----------------
__global__ void k_tables(const float* __restrict__ Wrel, const float* __restrict__ wrel,
                         const float* __restrict__ dre_emb, const float* __restrict__ dae_emb) {
    __shared__ float us[NH * 128];
    int tid = threadIdx.x;
    for (int id = tid; id < NH * 128; id += 256) {
        int h = id >> 7, k = id & 127;
        float s = 0.f;
#pragma unroll
        for (int j = 0; j < 16; j++) s += Wrel[k * 128 + h * 16 + j] * wrel[h * 16 + j];
        us[h * 128 + k] = s;
    }
    __syncthreads();
    for (int id = tid; id < 50 * NH; id += 256) {
        int r = id / NH, h = id % NH;
        float s = 0.f;
        for (int k = 0; k < 64; k++) s += dre_emb[r * 64 + k] * us[h * 128 + k];
        g_srel_dr[r * NH + h] = s;
    }
    for (int id = tid; id < 4 * NH; id += 256) {
        int a = id / NH, h = id % NH;
        float s = 0.f;
        for (int k = 0; k < 64; k++) s += dae_emb[a * 64 + k] * us[h * 128 + 64 + k];
        g_srel_da[a * NH + h] = s;
    }
}

// ---------------- compose scalar projection matrix B2 [256 x 32] (parallel) ----------------
// block k (0..255), warp h (0..7): s1 = Wv[k, h*32: ] . wsrc[h], s2 = . wtgt[h],
// s3 = Wn[k, :] . gate_w[256:, h]
__global__ void __launch_bounds__(256) k_prep(const float* __restrict__ Wv,
                                              const float* __restrict__ wsrc,
                                              const float* __restrict__ wtgt,
                                              const float* __restrict__ gatew,
                                              const float* __restrict__ Wn,
                                              const float* __restrict__ nbias) {
    int k = blockIdx.x;
    int lane = threadIdx.x & 31, h = threadIdx.x >> 5;
    float v = Wv[k * 256 + h * 32 + lane];
    float s1 = wsum(v * wsrc[h * 32 + lane]);
    float s2 = wsum(v * wtgt[h * 32 + lane]);
    float s3p = 0.f;
#pragma unroll
    for (int j = 0; j < 8; j++) {
        int t = j * 32 + lane;
        s3p += Wn[k * 256 + t] * gatew[(256 + t) * 8 + h];
    }
    float s3 = wsum(s3p);
    if (lane == 0) {
        g_B2[k * 32 + h] = s1;
        g_B2[k * 32 + 8 + h] = s2;
        g_B2[k * 32 + 16 + h] = gatew[k * 8 + h];
        g_B2[k * 32 + 24 + h] = s3;
    }
    if (k == 0) {
        float cp = 0.f;
#pragma unroll
        for (int j = 0; j < 8; j++) {
            int t = j * 32 + lane;
            cp += nbias[t] * gatew[(256 + t) * 8 + h];
        }
        float c = wsum(cp);
        if (lane == 0) g_cq[h] = c;
    }
}

// ---------------- CSR count + scan ----------------
__global__ void k_count(const int* __restrict__ ei) {
    int e = blockIdx.x * blockDim.x + threadIdx.x;
    if (e < N_EDGES) atomicAdd(&g_deg[ei[N_EDGES + e]], 1);
}

__global__ void k_scan() {  // 1 block, 1024 threads, warp-shuffle scan
    __shared__ int wsums[32];
    __shared__ int carry_s;
    int tid = threadIdx.x, lane = tid & 31, wid = tid >> 5;
    if (tid == 0) carry_s = 0;
    __syncthreads();
    for (int base = 0; base < N_NODES; base += 1024) {
        int i = base + tid;
        int v = (i < N_NODES) ? g_deg[i] : 0;
        int x = v;
#pragma unroll
        for (int o = 1; o < 32; o <<= 1) {
            int t = __shfl_up_sync(0xFFFFFFFFu, x, o);
            if (lane >= o) x += t;
        }
        if (lane == 31) wsums[wid] = x;
        __syncthreads();
        if (wid == 0) {
            int s = wsums[lane];
#pragma unroll
            for (int o = 1; o < 32; o <<= 1) {
                int t = __shfl_up_sync(0xFFFFFFFFu, s, o);
                if (lane >= o) s += t;
            }
            wsums[lane] = s;
        }
        __syncthreads();
        int wpre = wid ? wsums[wid - 1] : 0;
        int carry = carry_s;
        if (i < N_NODES) g_off[i] = carry + wpre + x - v;
        int tot = wsums[31];
        __syncthreads();
        if (tid == 0) carry_s = carry + tot;
        __syncthreads();
    }
    if (threadIdx.x == 0) g_off[N_NODES] = carry_s;
}

// ---------------- fused GEMM: [N,256] @ [256, 256|32] -> value | scal ----------------
#define BM 128
#define BN 64
#define BK 16
#define ASTR 132
#define BSTR 68

__global__ void __launch_bounds__(256) k_gemm(const float* __restrict__ inp,
                                              const float* __restrict__ Wv) {
    __shared__ float As[2][BK][ASTR];
    __shared__ float Bs[2][BK][BSTR];
    int tid = threadIdx.x;
    int bx = blockIdx.x, by = blockIdx.y;
    int row0 = by * BM;
    bool scal = (bx == 4);
    int col0 = bx * BN;

    int am = tid >> 2, ak = (tid & 3) << 2;
    int bk = tid >> 4, bc = (tid & 15) << 2;
    int tx = tid & 15, ty = tid >> 4;

    float acc[8][4];
#pragma unroll
    for (int i = 0; i < 8; i++)
#pragma unroll
        for (int j = 0; j < 4; j++) acc[i][j] = 0.f;

    int r0i = row0 + am, r1i = row0 + am + 64;
    bool v0 = r0i < N_NODES, v1 = r1i < N_NODES;
    float4 ra0, ra1, rb;
    const float4 z4 = make_float4(0.f, 0.f, 0.f, 0.f);

    ra0 = v0 ? *(const float4*)(inp + (size_t)r0i * 256 + ak) : z4;
    ra1 = v1 ? *(const float4*)(inp + (size_t)r1i * 256 + ak) : z4;
    if (!scal) rb = *(const float4*)(Wv + (size_t)bk * 256 + col0 + bc);
    else rb = (bc < 32) ? *(const float4*)(g_B2 + bk * 32 + bc) : z4;

    As[0][ak + 0][am] = ra0.x; As[0][ak + 1][am] = ra0.y;
    As[0][ak + 2][am] = ra0.z; As[0][ak + 3][am] = ra0.w;
    As[0][ak + 0][am + 64] = ra1.x; As[0][ak + 1][am + 64] = ra1.y;
    As[0][ak + 2][am + 64] = ra1.z; As[0][ak + 3][am + 64] = ra1.w;
    *(float4*)&Bs[0][bk][bc] = rb;
    __syncthreads();

    for (int t = 0; t < 16; t++) {
        int buf = t & 1;
        if (t < 15) {
            int k0 = (t + 1) * BK;
            ra0 = v0 ? *(const float4*)(inp + (size_t)r0i * 256 + k0 + ak) : z4;
            ra1 = v1 ? *(const float4*)(inp + (size_t)r1i * 256 + k0 + ak) : z4;
            if (!scal) rb = *(const float4*)(Wv + (size_t)(k0 + bk) * 256 + col0 + bc);
            else rb = (bc < 32) ? *(const float4*)(g_B2 + (k0 + bk) * 32 + bc) : z4;
        }
#pragma unroll
        for (int kk = 0; kk < BK; kk++) {
            float4 a0 = *(const float4*)&As[buf][kk][ty * 8];
            float4 a1 = *(const float4*)&As[buf][kk][ty * 8 + 4];
            float4 b4 = *(const float4*)&Bs[buf][kk][tx * 4];
            float a[8] = {a0.x, a0.y, a0.z, a0.w, a1.x, a1.y, a1.z, a1.w};
            float b[4] = {b4.x, b4.y, b4.z, b4.w};
#pragma unroll
            for (int i = 0; i < 8; i++)
#pragma unroll
                for (int j = 0; j < 4; j++) acc[i][j] += a[i] * b[j];
        }
        if (t < 15) {
            int nb = buf ^ 1;
            As[nb][ak + 0][am] = ra0.x; As[nb][ak + 1][am] = ra0.y;
            As[nb][ak + 2][am] = ra0.z; As[nb][ak + 3][am] = ra0.w;
            As[nb][ak + 0][am + 64] = ra1.x; As[nb][ak + 1][am + 64] = ra1.y;
            As[nb][ak + 2][am + 64] = ra1.z; As[nb][ak + 3][am + 64] = ra1.w;
            *(float4*)&Bs[nb][bk][bc] = rb;
            __syncthreads();
        }
    }

#pragma unroll
    for (int i = 0; i < 8; i++) {
        int r = row0 + ty * 8 + i;
        if (r >= N_NODES) continue;
        float4 o = make_float4(acc[i][0], acc[i][1], acc[i][2], acc[i][3]);
        if (!scal) {
            *(float4*)(g_value + (size_t)r * 256 + col0 + tx * 4) = o;
        } else if (tx * 4 < 32) {
            *(float4*)(g_scal + (size_t)r * 32 + tx * 4) = o;
        }
    }
}

// ---------------- CSR fill + fused global score max ----------------
__global__ void k_fillmax(const int* __restrict__ ei, const int* __restrict__ dre,
                          const int* __restrict__ dae) {
    int e = blockIdx.x * blockDim.x + threadIdx.x;
    float mv = -1e30f, mr = -1e30f;
    if (e < N_EDGES) {
        int src = ei[e], tgt = ei[N_EDGES + e], dr = dre[e], da = dae[e];
        int pos = g_off[tgt] + atomicAdd(&g_cursor[tgt], 1);
        g_esort[pos] = src | (dr << 16) | (da << 22);
#pragma unroll
        for (int h = 0; h < NH; h++) {
            float st = g_scal[tgt * 32 + 8 + h];
            float rv = g_scal[src * 32 + h] + st;
            float rr = g_srel_dr[dr * 8 + h] + g_srel_da[da * 8 + h] + st;
            mv = fmaxf(mv, rv);
            mr = fmaxf(mr, rr);
        }
    }
#pragma unroll
    for (int o = 16; o; o >>= 1) {
        mv = fmaxf(mv, __shfl_xor_sync(0xFFFFFFFFu, mv, o));
        mr = fmaxf(mr, __shfl_xor_sync(0xFFFFFFFFu, mr, o));
    }
    if ((threadIdx.x & 31) == 0) {
        atomicMax(&g_maxraw[0], encodef(mv));
        atomicMax(&g_maxraw[1], encodef(mr));
    }
}

// ---------------- aggregation + epilogue: one block per target node ----------------
__global__ void __launch_bounds__(256) k_agg(const float* __restrict__ fpw,
                                             const float* __restrict__ fpb,
                                             const float* __restrict__ gateb,
                                             const float* __restrict__ fbias,
                                             float* __restrict__ out) {
    __shared__ float tdr[50 * NH];
    __shared__ float tda[4 * NH];
    __shared__ float cat[8][64];
    int tid = threadIdx.x;
    int lane = tid & 31, h = tid >> 5;
    for (int i = tid; i < 50 * NH; i += 256) tdr[i] = g_srel_dr[i];
    if (tid < 32) tda[tid] = g_srel_da[tid];
    __syncthreads();

    int n = blockIdx.x;
    float Mv = leaky(decodef(g_maxraw[0]));
    float Mr = leaky(decodef(g_maxraw[1]));
    int e0 = g_off[n], e1 = g_off[n + 1];
    float stgt = g_scal[n * 32 + 8 + h];
    float accv = 0.f, accr = 0.f, denv = 0.f, denr = 0.f, accq = 0.f;
    for (int p = e0; p < e1; p++) {
        int pk = g_esort[p];
        int src = pk & 0xFFFF;
        int dr = (pk >> 16) & 0x3F;
        int da = (pk >> 22) & 0x3;
        float ssrc = g_scal[src * 32 + h];
        float q = g_scal[src * 32 + 24 + h];
        float rv = ssrc + stgt;
        float rr = tdr[dr * 8 + h] + tda[da * 8 + h] + stgt;
        float ev = __expf(leaky(rv) - Mv);
        float er = __expf(leaky(rr) - Mr);
        denv += ev;
        denr += er;
        accq += q;
        float x = g_value[(size_t)src * 256 + h * 32 + lane];
        accv += ev * x;
        accr += er * x;
    }
    accv /= (denv + EPS);
    accr /= (denr + EPS);

    cat[h][lane] = accv;
    cat[h][32 + lane] = accr;
    __syncthreads();

    int deg = e1 - e0;
    float nbterm = deg > 0 ? accq / (float)deg + g_cq[h] : 0.f;
    float gate = 1.f / (1.f + __expf(-(g_scal[n * 32 + 16 + h] + nbterm + gateb[h])));

    float ho = fpb[h * 32 + lane];
#pragma unroll
    for (int d = 0; d < 64; d++) ho += cat[h][d] * fpw[h * 2048 + d * 32 + lane];

    out[(size_t)n * 256 + h * 32 + lane] = ho * gate + fbias[h * 32 + lane];
}

// ---------------- launcher ----------------
extern "C" void kernel_launch(void* const* d_in, const int* in_sizes, int n_in,
                              void* d_out, int out_size) {
    const float* inp = (const float*)d_in[0];
    const float* Wv = (const float*)d_in[2];
    const float* Wrel = (const float*)d_in[3];
    const float* dre_emb = (const float*)d_in[4];
    const float* dae_emb = (const float*)d_in[5];
    const float* wsrc = (const float*)d_in[6];
    const float* wtgt = (const float*)d_in[7];
    const float* wrel = (const float*)d_in[8];
    const float* fpw = (const float*)d_in[9];
    const float* fpb = (const float*)d_in[10];
    const float* Wn = (const float*)d_in[11];
    const float* nbias = (const float*)d_in[12];
    const float* gatew = (const float*)d_in[13];
    const float* gateb = (const float*)d_in[14];
    const float* fbias = (const float*)d_in[15];
    const int* ei = (const int*)d_in[16];
    const int* dre = (const int*)d_in[17];
    const int* dae = (const int*)d_in[18];
    float* out = (float*)d_out;

    k_tables<<<1, 256>>>(Wrel, wrel, dre_emb, dae_emb);             // 1
    k_prep<<<256, 256>>>(Wv, wsrc, wtgt, gatew, Wn, nbias);         // 2
    k_init<<<(N_NODES + 255) / 256, 256>>>();                       // 3
    k_gemm<<<dim3(5, (N_NODES + BM - 1) / BM), 256>>>(inp, Wv);     // 4 (profiled)
    k_count<<<(N_EDGES + 255) / 256, 256>>>(ei);                    // 5
    k_scan<<<1, 1024>>>();                                          // 6
    k_fillmax<<<(N_EDGES + 255) / 256, 256>>>(ei, dre, dae);        // 7
    k_agg<<<N_NODES, 256>>>(fpw, fpb, gateb, fbias, out);           // 8
}

// round 4
// speedup vs baseline: 2.5656x; 1.1572x over previous
#include <cuda_runtime.h>

#define N_NODES 20000
#define N_EDGES 160000
#define NH 8
#define EPS 1e-12f
#define SLOPE 0.2f

// ---------------- scratch ----------------
__device__ float g_value[N_NODES * 256];
__device__ float g_scal[N_NODES * 32];   // 0-7 ssrc | 8-15 stgt | 16-23 gate1 | 24-31 q
__device__ float g_B2[256 * 32];
__device__ float g_cq[NH];
__device__ float g_srel_dr[50 * NH];
__device__ float g_srel_da[4 * NH];
__device__ float g_tabmax[2];            // max tdr, max tda
__device__ int g_deg[N_NODES];
__device__ int g_cursor[N_NODES];
__device__ int g_off[N_NODES + 1];
__device__ int g_esort[N_EDGES];
__device__ unsigned g_maxraw[2];         // encoded max ssrc, max stgt

__device__ __forceinline__ float leaky(float x) { return x >= 0.f ? x : SLOPE * x; }

__device__ __forceinline__ float wsum(float v) {
#pragma unroll
    for (int o = 16; o; o >>= 1) v += __shfl_xor_sync(0xFFFFFFFFu, v, o);
    return v;
}

__device__ __forceinline__ unsigned encodef(float f) {
    unsigned b = __float_as_uint(f);
    return (b & 0x80000000u) ? ~b : (b | 0x80000000u);
}
__device__ __forceinline__ float decodef(unsigned u) {
    unsigned b = (u & 0x80000000u) ? (u & 0x7FFFFFFFu) : ~u;
    return __uint_as_float(b);
}

// ---------------- init ----------------
__global__ void k_init() {
    int i = blockIdx.x * blockDim.x + threadIdx.x;
    if (i < N_NODES) { g_deg[i] = 0; g_cursor[i] = 0; }
    if (i < 2) g_maxraw[i] = 0u;
}

// ---------------- CSR count + scan + fill ----------------
__global__ void k_count(const int* __restrict__ ei) {
    int e = blockIdx.x * blockDim.x + threadIdx.x;
    if (e < N_EDGES) atomicAdd(&g_deg[ei[N_EDGES + e]], 1);
}

__global__ void k_scan() {
    __shared__ int wsums[32];
    __shared__ int carry_s;
    int tid = threadIdx.x, lane = tid & 31, wid = tid >> 5;
    if (tid == 0) carry_s = 0;
    __syncthreads();
    for (int base = 0; base < N_NODES; base += 1024) {
        int i = base + tid;
        int v = (i < N_NODES) ? g_deg[i] : 0;
        int x = v;
#pragma unroll
        for (int o = 1; o < 32; o <<= 1) {
            int t = __shfl_up_sync(0xFFFFFFFFu, x, o);
            if (lane >= o) x += t;
        }
        if (lane == 31) wsums[wid] = x;
        __syncthreads();
        if (wid == 0) {
            int s = wsums[lane];
#pragma unroll
            for (int o = 1; o < 32; o <<= 1) {
                int t = __shfl_up_sync(0xFFFFFFFFu, s, o);
                if (lane >= o) s += t;
            }
            wsums[lane] = s;
        }
        __syncthreads();
        int wpre = wid ? wsums[wid - 1] : 0;
        int carry = carry_s;
        if (i < N_NODES) g_off[i] = carry + wpre + x - v;
        int tot = wsums[31];
        __syncthreads();
        if (tid == 0) carry_s = carry + tot;
        __syncthreads();
    }
    if (threadIdx.x == 0) g_off[N_NODES] = carry_s;
}

__global__ void k_fill(const int* __restrict__ ei, const int* __restrict__ dre,
                       const int* __restrict__ dae) {
    int e = blockIdx.x * blockDim.x + threadIdx.x;
    if (e >= N_EDGES) return;
    int src = ei[e], tgt = ei[N_EDGES + e];
    int pos = g_off[tgt] + atomicAdd(&g_cursor[tgt], 1);
    g_esort[pos] = src | (dre[e] << 16) | (dae[e] << 22);
}

// ---------------- relation score tables (+ their maxes) ----------------
__global__ void k_tables(const float* __restrict__ Wrel, const float* __restrict__ wrel,
                         const float* __restrict__ dre_emb, const float* __restrict__ dae_emb) {
    __shared__ float us[NH * 128];
    __shared__ unsigned sm0, sm1;
    int tid = threadIdx.x;
    if (tid == 0) { sm0 = 0u; sm1 = 0u; }
    for (int id = tid; id < NH * 128; id += 256) {
        int h = id >> 7, k = id & 127;
        float s = 0.f;
#pragma unroll
        for (int j = 0; j < 16; j++) s += Wrel[k * 128 + h * 16 + j] * wrel[h * 16 + j];
        us[h * 128 + k] = s;
    }
    __syncthreads();
    float mdr = -1e30f, mda = -1e30f;
    for (int id = tid; id < 50 * NH; id += 256) {
        int r = id / NH, h = id % NH;
        float s = 0.f;
        for (int k = 0; k < 64; k++) s += dre_emb[r * 64 + k] * us[h * 128 + k];
        g_srel_dr[r * NH + h] = s;
        mdr = fmaxf(mdr, s);
    }
    for (int id = tid; id < 4 * NH; id += 256) {
        int a = id / NH, h = id % NH;
        float s = 0.f;
        for (int k = 0; k < 64; k++) s += dae_emb[a * 64 + k] * us[h * 128 + 64 + k];
        g_srel_da[a * NH + h] = s;
        mda = fmaxf(mda, s);
    }
    atomicMax(&sm0, encodef(mdr));
    atomicMax(&sm1, encodef(mda));
    __syncthreads();
    if (tid == 0) {
        g_tabmax[0] = decodef(sm0);
        g_tabmax[1] = decodef(sm1);
    }
}

// ---------------- compose scalar projection matrix B2 [256 x 32] ----------------
__global__ void __launch_bounds__(256) k_prep(const float* __restrict__ Wv,
                                              const float* __restrict__ wsrc,
                                              const float* __restrict__ wtgt,
                                              const float* __restrict__ gatew,
                                              const float* __restrict__ Wn,
                                              const float* __restrict__ nbias) {
    int k = blockIdx.x;
    int lane = threadIdx.x & 31, h = threadIdx.x >> 5;
    float v = Wv[k * 256 + h * 32 + lane];
    float s1 = wsum(v * wsrc[h * 32 + lane]);
    float s2 = wsum(v * wtgt[h * 32 + lane]);
    float s3p = 0.f;
#pragma unroll
    for (int j = 0; j < 8; j++) {
        int t = j * 32 + lane;
        s3p += Wn[k * 256 + t] * gatew[(256 + t) * 8 + h];
    }
    float s3 = wsum(s3p);
    if (lane == 0) {
        g_B2[k * 32 + h] = s1;
        g_B2[k * 32 + 8 + h] = s2;
        g_B2[k * 32 + 16 + h] = gatew[k * 8 + h];
        g_B2[k * 32 + 24 + h] = s3;
    }
    if (k == 0) {
        float cp = 0.f;
#pragma unroll
        for (int j = 0; j < 8; j++) {
            int t = j * 32 + lane;
            cp += nbias[t] * gatew[(256 + t) * 8 + h];
        }
        float c = wsum(cp);
        if (lane == 0) g_cq[h] = c;
    }
}

// ---------------- fused GEMM: [N,256] @ [256, 256|32] -> value | scal ----------------
#define BM 128
#define BN 64
#define BK 16
#define ASTR 132
#define BSTR 68

__global__ void __launch_bounds__(256) k_gemm(const float* __restrict__ inp,
                                              const float* __restrict__ Wv) {
    __shared__ float As[2][BK][ASTR];
    __shared__ float Bs[2][BK][BSTR];
    int tid = threadIdx.x;
    int bx = blockIdx.x, by = blockIdx.y;
    int row0 = by * BM;
    bool scal = (bx == 4);
    int col0 = bx * BN;

    int am = tid >> 2, ak = (tid & 3) << 2;
    int bk = tid >> 4, bc = (tid & 15) << 2;
    int tx = tid & 15, ty = tid >> 4;

    float acc[8][4];
#pragma unroll
    for (int i = 0; i < 8; i++)
#pragma unroll
        for (int j = 0; j < 4; j++) acc[i][j] = 0.f;

    int r0i = row0 + am, r1i = row0 + am + 64;
    bool v0 = r0i < N_NODES, v1 = r1i < N_NODES;
    float4 ra0, ra1, rb;
    const float4 z4 = make_float4(0.f, 0.f, 0.f, 0.f);

    ra0 = v0 ? *(const float4*)(inp + (size_t)r0i * 256 + ak) : z4;
    ra1 = v1 ? *(const float4*)(inp + (size_t)r1i * 256 + ak) : z4;
    if (!scal) rb = *(const float4*)(Wv + (size_t)bk * 256 + col0 + bc);
    else rb = (bc < 32) ? *(const float4*)(g_B2 + bk * 32 + bc) : z4;

    As[0][ak + 0][am] = ra0.x; As[0][ak + 1][am] = ra0.y;
    As[0][ak + 2][am] = ra0.z; As[0][ak + 3][am] = ra0.w;
    As[0][ak + 0][am + 64] = ra1.x; As[0][ak + 1][am + 64] = ra1.y;
    As[0][ak + 2][am + 64] = ra1.z; As[0][ak + 3][am + 64] = ra1.w;
    *(float4*)&Bs[0][bk][bc] = rb;
    __syncthreads();

    for (int t = 0; t < 16; t++) {
        int buf = t & 1;
        if (t < 15) {
            int k0 = (t + 1) * BK;
            ra0 = v0 ? *(const float4*)(inp + (size_t)r0i * 256 + k0 + ak) : z4;
            ra1 = v1 ? *(const float4*)(inp + (size_t)r1i * 256 + k0 + ak) : z4;
            if (!scal) rb = *(const float4*)(Wv + (size_t)(k0 + bk) * 256 + col0 + bc);
            else rb = (bc < 32) ? *(const float4*)(g_B2 + (k0 + bk) * 32 + bc) : z4;
        }
#pragma unroll
        for (int kk = 0; kk < BK; kk++) {
            float4 a0 = *(const float4*)&As[buf][kk][ty * 8];
            float4 a1 = *(const float4*)&As[buf][kk][ty * 8 + 4];
            float4 b4 = *(const float4*)&Bs[buf][kk][tx * 4];
            float a[8] = {a0.x, a0.y, a0.z, a0.w, a1.x, a1.y, a1.z, a1.w};
            float b[4] = {b4.x, b4.y, b4.z, b4.w};
#pragma unroll
            for (int i = 0; i < 8; i++)
#pragma unroll
                for (int j = 0; j < 4; j++) acc[i][j] += a[i] * b[j];
        }
        if (t < 15) {
            int nb = buf ^ 1;
            As[nb][ak + 0][am] = ra0.x; As[nb][ak + 1][am] = ra0.y;
            As[nb][ak + 2][am] = ra0.z; As[nb][ak + 3][am] = ra0.w;
            As[nb][ak + 0][am + 64] = ra1.x; As[nb][ak + 1][am + 64] = ra1.y;
            As[nb][ak + 2][am + 64] = ra1.z; As[nb][ak + 3][am + 64] = ra1.w;
            *(float4*)&Bs[nb][bk][bc] = rb;
            __syncthreads();
        }
    }

#pragma unroll
    for (int i = 0; i < 8; i++) {
        int r = row0 + ty * 8 + i;
        if (r >= N_NODES) continue;
        float4 o = make_float4(acc[i][0], acc[i][1], acc[i][2], acc[i][3]);
        if (!scal) {
            *(float4*)(g_value + (size_t)r * 256 + col0 + tx * 4) = o;
        } else if (tx * 4 < 32) {
            *(float4*)(g_scal + (size_t)r * 32 + tx * 4) = o;
        }
    }
}

// ---------------- per-column maxes of ssrc / stgt ----------------
__global__ void k_nodemax() {
    int i = blockIdx.x * blockDim.x + threadIdx.x;
    float ms = -1e30f, mt = -1e30f;
    if (i < N_NODES * 32) {
        int c = i & 31;
        float v = g_scal[i];
        if (c < 8) ms = v;
        else if (c < 16) mt = v;
    }
#pragma unroll
    for (int o = 16; o; o >>= 1) {
        ms = fmaxf(ms, __shfl_xor_sync(0xFFFFFFFFu, ms, o));
        mt = fmaxf(mt, __shfl_xor_sync(0xFFFFFFFFu, mt, o));
    }
    if ((threadIdx.x & 31) == 0) {
        atomicMax(&g_maxraw[0], encodef(ms));
        atomicMax(&g_maxraw[1], encodef(mt));
    }
}

// ---------------- aggregation + epilogue: one WARP per node, 8 nodes per block ----------------
__global__ void __launch_bounds__(256) k_agg(const float* __restrict__ fpw,
                                             const float* __restrict__ fpb,
                                             const float* __restrict__ gateb,
                                             const float* __restrict__ fbias,
                                             float* __restrict__ out) {
    __shared__ float tdr[50 * NH];
    __shared__ float tda[4 * NH];
    __shared__ float cat_s[8][8][64];  // [node][head][2*DV]
    __shared__ float gate_s[8][8];     // [node][head]
    __shared__ int deg_s[8];
    int tid = threadIdx.x, lane = tid & 31, w = tid >> 5;
    for (int i = tid; i < 50 * NH; i += 256) tdr[i] = g_srel_dr[i];
    if (tid < 32) tda[tid] = g_srel_da[tid];
    __syncthreads();

    int n = blockIdx.x * 8 + w;  // 2500 * 8 == 20000 exactly
    float maxssrc = decodef(g_maxraw[0]);
    float maxstgt = decodef(g_maxraw[1]);
    float Mv = leaky(maxssrc + maxstgt);
    float Mr = leaky(g_tabmax[0] + g_tabmax[1] + maxstgt);

    int e0 = g_off[n], e1 = g_off[n + 1];
    float nscal = g_scal[n * 32 + lane];
    float stgt_sh = __shfl_sync(0xFFFFFFFFu, nscal, (lane & 7) + 8);

    float accv[8], accr[8];
#pragma unroll
    for (int h = 0; h < 8; h++) { accv[h] = 0.f; accr[h] = 0.f; }
    float den_l = 0.f, accq_l = 0.f;

    int soff = (lane < 8) ? lane : 16 + lane;  // lanes 8..15 -> 24+(lane-8)

    int pk = (e0 < e1) ? g_esort[e0] : 0;
    for (int p = e0; p < e1; p++) {
        int pk_next = (p + 1 < e1) ? g_esort[p + 1] : 0;
        int src = pk & 0xFFFF;
        int dr = (pk >> 16) & 0x3F;
        int da = (pk >> 22) & 0x3;
        float sv = (lane < 16) ? g_scal[src * 32 + soff] : 0.f;
        float x[8];
#pragma unroll
        for (int h = 0; h < 8; h++) x[h] = g_value[(size_t)src * 256 + h * 32 + lane];
        float arg;
        if (lane < 8)
            arg = leaky(sv + stgt_sh) - Mv;
        else
            arg = leaky(tdr[dr * 8 + (lane & 7)] + tda[da * 8 + (lane & 7)] + stgt_sh) - Mr;
        float e_l = __expf(arg);
        if (lane < 16) den_l += e_l;
        if (lane >= 8 && lane < 16) accq_l += sv;
#pragma unroll
        for (int h = 0; h < 8; h++) {
            float ev = __shfl_sync(0xFFFFFFFFu, e_l, h);
            float er = __shfl_sync(0xFFFFFFFFu, e_l, 8 + h);
            accv[h] += ev * x[h];
            accr[h] += er * x[h];
        }
        pk = pk_next;
    }

    int deg = e1 - e0;
#pragma unroll
    for (int h = 0; h < 8; h++) {
        float dv = __shfl_sync(0xFFFFFFFFu, den_l, h) + EPS;
        float drr = __shfl_sync(0xFFFFFFFFu, den_l, 8 + h) + EPS;
        cat_s[w][h][lane] = accv[h] / dv;
        cat_s[w][h][32 + lane] = accr[h] / drr;
    }
    // gate (lanes 0..7: head = lane)
    if (lane < 8) {
        float g1 = __shfl_sync(0x000000FFu, nscal, 16 + lane);  // careful: need lane16.. use full path below
        g1 = 0.f;  // recomputed below
    }
    // compute gate with full-warp shuffles
    {
        float g1 = __shfl_sync(0xFFFFFFFFu, nscal, 16 + (lane & 7));
        float aq = __shfl_sync(0xFFFFFFFFu, accq_l, 8 + (lane & 7));
        if (lane < 8) {
            float nbterm = deg > 0 ? aq / (float)deg + g_cq[lane] : 0.f;
            gate_s[w][lane] = 1.f / (1.f + __expf(-(g1 + nbterm + gateb[lane])));
        }
    }
    if (lane == 0) deg_s[w] = deg;
    __syncthreads();

    // ---- epilogue: warp w == head h, loops over the block's 8 nodes ----
    int h = w;
    float wreg[64];
#pragma unroll
    for (int d = 0; d < 64; d++) wreg[d] = fpw[h * 2048 + d * 32 + lane];
    float bias = fpb[h * 32 + lane];
    float fb = fbias[h * 32 + lane];
    int nbase = blockIdx.x * 8;
#pragma unroll
    for (int nn = 0; nn < 8; nn++) {
        float ho = bias;
#pragma unroll
        for (int d4 = 0; d4 < 16; d4++) {
            float4 c4 = *(const float4*)&cat_s[nn][h][d4 * 4];
            ho += c4.x * wreg[d4 * 4 + 0] + c4.y * wreg[d4 * 4 + 1] +
                  c4.z * wreg[d4 * 4 + 2] + c4.w * wreg[d4 * 4 + 3];
        }
        float gate = gate_s[nn][h];
        out[(size_t)(nbase + nn) * 256 + h * 32 + lane] = ho * gate + fb;
    }
}

// ---------------- launcher ----------------
extern "C" void kernel_launch(void* const* d_in, const int* in_sizes, int n_in,
                              void* d_out, int out_size) {
    const float* inp = (const float*)d_in[0];
    const float* Wv = (const float*)d_in[2];
    const float* Wrel = (const float*)d_in[3];
    const float* dre_emb = (const float*)d_in[4];
    const float* dae_emb = (const float*)d_in[5];
    const float* wsrc = (const float*)d_in[6];
    const float* wtgt = (const float*)d_in[7];
    const float* wrel = (const float*)d_in[8];
    const float* fpw = (const float*)d_in[9];
    const float* fpb = (const float*)d_in[10];
    const float* Wn = (const float*)d_in[11];
    const float* nbias = (const float*)d_in[12];
    const float* gatew = (const float*)d_in[13];
    const float* gateb = (const float*)d_in[14];
    const float* fbias = (const float*)d_in[15];
    const int* ei = (const int*)d_in[16];
    const int* dre = (const int*)d_in[17];
    const int* dae = (const int*)d_in[18];
    float* out = (float*)d_out;

    k_init<<<(N_NODES + 255) / 256, 256>>>();                       // 1
    k_count<<<(N_EDGES + 255) / 256, 256>>>(ei);                    // 2
    k_scan<<<1, 1024>>>();                                          // 3
    k_fill<<<(N_EDGES + 255) / 256, 256>>>(ei, dre, dae);           // 4 (profiled)
    k_tables<<<1, 256>>>(Wrel, wrel, dre_emb, dae_emb);             // 5
    k_prep<<<256, 256>>>(Wv, wsrc, wtgt, gatew, Wn, nbias);         // 6
    k_gemm<<<dim3(5, (N_NODES + BM - 1) / BM), 256>>>(inp, Wv);     // 7
    k_nodemax<<<(N_NODES * 32 + 255) / 256, 256>>>();               // 8
    k_agg<<<2500, 256>>>(fpw, fpb, gateb, fbias, out);              // 9
}

// round 5
// speedup vs baseline: 3.1333x; 1.2213x over previous
#include <cuda_runtime.h>

#define N_NODES 20000
#define N_EDGES 160000
#define NH 8
#define EPS 1e-12f
#define SLOPE 0.2f

typedef unsigned long long u64;

// ---------------- scratch ----------------
__device__ float g_value[N_NODES * 256];
__device__ float g_scal[N_NODES * 32];   // 0-7 ssrc | 8-15 stgt | 16-23 gate1 | 24-31 q
__device__ float g_B2[256 * 32];
__device__ float g_cq[NH];
__device__ float g_srel_dr[50 * NH];
__device__ float g_srel_da[4 * NH];
__device__ float g_tabmax[2];
__device__ int g_deg[N_NODES];
__device__ int g_cursor[N_NODES];
__device__ int g_off[N_NODES + 1];
__device__ int g_esort[N_EDGES];
__device__ unsigned g_maxraw[2];         // encoded max ssrc, max stgt

__device__ __forceinline__ float leaky(float x) { return x >= 0.f ? x : SLOPE * x; }

__device__ __forceinline__ float wsum(float v) {
#pragma unroll
    for (int o = 16; o; o >>= 1) v += __shfl_xor_sync(0xFFFFFFFFu, v, o);
    return v;
}

__device__ __forceinline__ unsigned encodef(float f) {
    unsigned b = __float_as_uint(f);
    return (b & 0x80000000u) ? ~b : (b | 0x80000000u);
}
__device__ __forceinline__ float decodef(unsigned u) {
    unsigned b = (u & 0x80000000u) ? (u & 0x7FFFFFFFu) : ~u;
    return __uint_as_float(b);
}

__device__ __forceinline__ void ffma2(u64& d, u64 a, u64 b) {
    asm("fma.rn.f32x2 %0, %1, %2, %0;" : "+l"(d) : "l"(a), "l"(b));
}
__device__ __forceinline__ u64 bcast2(float x) {
    u64 r;
    unsigned u = __float_as_uint(x);
    asm("mov.b64 %0, {%1, %2};" : "=l"(r) : "r"(u), "r"(u));
    return r;
}
__device__ __forceinline__ void unpack2(u64 v, float& lo, float& hi) {
    unsigned a, b;
    asm("mov.b64 {%0, %1}, %2;" : "=r"(a), "=r"(b) : "l"(v));
    lo = __uint_as_float(a);
    hi = __uint_as_float(b);
}

// ---------------- init ----------------
__global__ void k_init() {
    int i = blockIdx.x * blockDim.x + threadIdx.x;
    if (i < N_NODES) { g_deg[i] = 0; g_cursor[i] = 0; }
    if (i < 2) g_maxraw[i] = 0u;
}

// ---------------- pre: tables(b0) | prep(b1..256) | count(b257..881) ----------------
__global__ void __launch_bounds__(256) k_pre(
    const float* __restrict__ Wrel, const float* __restrict__ wrel,
    const float* __restrict__ dre_emb, const float* __restrict__ dae_emb,
    const float* __restrict__ Wv, const float* __restrict__ wsrc,
    const float* __restrict__ wtgt, const float* __restrict__ gatew,
    const float* __restrict__ Wn, const float* __restrict__ nbias,
    const int* __restrict__ ei) {
    int b = blockIdx.x;
    int tid = threadIdx.x;
    if (b == 0) {
        // relation score tables + their maxes
        __shared__ float us[NH * 128];
        __shared__ unsigned sm0, sm1;
        if (tid == 0) { sm0 = 0u; sm1 = 0u; }
        for (int id = tid; id < NH * 128; id += 256) {
            int h = id >> 7, k = id & 127;
            float s = 0.f;
#pragma unroll
            for (int j = 0; j < 16; j++) s += Wrel[k * 128 + h * 16 + j] * wrel[h * 16 + j];
            us[h * 128 + k] = s;
        }
        __syncthreads();
        float mdr = -1e30f, mda = -1e30f;
        for (int id = tid; id < 50 * NH; id += 256) {
            int r = id / NH, h = id % NH;
            float s = 0.f;
            for (int k = 0; k < 64; k++) s += dre_emb[r * 64 + k] * us[h * 128 + k];
            g_srel_dr[r * NH + h] = s;
            mdr = fmaxf(mdr, s);
        }
        for (int id = tid; id < 4 * NH; id += 256) {
            int a = id / NH, h = id % NH;
            float s = 0.f;
            for (int k = 0; k < 64; k++) s += dae_emb[a * 64 + k] * us[h * 128 + 64 + k];
            g_srel_da[a * NH + h] = s;
            mda = fmaxf(mda, s);
        }
        atomicMax(&sm0, encodef(mdr));
        atomicMax(&sm1, encodef(mda));
        __syncthreads();
        if (tid == 0) {
            g_tabmax[0] = decodef(sm0);
            g_tabmax[1] = decodef(sm1);
        }
    } else if (b <= 256) {
        // compose B2 row k
        int k = b - 1;
        int lane = tid & 31, h = tid >> 5;
        float v = Wv[k * 256 + h * 32 + lane];
        float s1 = wsum(v * wsrc[h * 32 + lane]);
        float s2 = wsum(v * wtgt[h * 32 + lane]);
        float s3p = 0.f;
#pragma unroll
        for (int j = 0; j < 8; j++) {
            int t = j * 32 + lane;
            s3p += Wn[k * 256 + t] * gatew[(256 + t) * 8 + h];
        }
        float s3 = wsum(s3p);
        if (lane == 0) {
            g_B2[k * 32 + h] = s1;
            g_B2[k * 32 + 8 + h] = s2;
            g_B2[k * 32 + 16 + h] = gatew[k * 8 + h];
            g_B2[k * 32 + 24 + h] = s3;
        }
        if (k == 0) {
            float cp = 0.f;
#pragma unroll
            for (int j = 0; j < 8; j++) {
                int t = j * 32 + lane;
                cp += nbias[t] * gatew[(256 + t) * 8 + h];
            }
            float c = wsum(cp);
            if (lane == 0) g_cq[h] = c;
        }
    } else {
        int e = (b - 257) * 256 + tid;
        if (e < N_EDGES) atomicAdd(&g_deg[ei[N_EDGES + e]], 1);
    }
}

// ---------------- scan ----------------
__global__ void k_scan() {
    __shared__ int wsums[32];
    __shared__ int carry_s;
    int tid = threadIdx.x, lane = tid & 31, wid = tid >> 5;
    if (tid == 0) carry_s = 0;
    __syncthreads();
    for (int base = 0; base < N_NODES; base += 1024) {
        int i = base + tid;
        int v = (i < N_NODES) ? g_deg[i] : 0;
        int x = v;
#pragma unroll
        for (int o = 1; o < 32; o <<= 1) {
            int t = __shfl_up_sync(0xFFFFFFFFu, x, o);
            if (lane >= o) x += t;
        }
        if (lane == 31) wsums[wid] = x;
        __syncthreads();
        if (wid == 0) {
            int s = wsums[lane];
#pragma unroll
            for (int o = 1; o < 32; o <<= 1) {
                int t = __shfl_up_sync(0xFFFFFFFFu, s, o);
                if (lane >= o) s += t;
            }
            wsums[lane] = s;
        }
        __syncthreads();
        int wpre = wid ? wsums[wid - 1] : 0;
        int carry = carry_s;
        if (i < N_NODES) g_off[i] = carry + wpre + x - v;
        int tot = wsums[31];
        __syncthreads();
        if (tid == 0) carry_s = carry + tot;
        __syncthreads();
    }
    if (threadIdx.x == 0) g_off[N_NODES] = carry_s;
}

// ---------------- fused GEMM (FFMA2) + nodemax + CSR fill ----------------
#define BM 128
#define BN 64
#define BK 16
#define ASTR 132
#define BSTR 68

__global__ void __launch_bounds__(256) k_gemm(const float* __restrict__ inp,
                                              const float* __restrict__ Wv,
                                              const int* __restrict__ ei,
                                              const int* __restrict__ dre,
                                              const int* __restrict__ dae) {
    __shared__ float As[2][BK][ASTR];
    __shared__ float Bs[2][BK][BSTR];
    int tid = threadIdx.x;
    int bx = blockIdx.x, by = blockIdx.y;

    if (bx == 5) {
        // ---- CSR fill (hidden under GEMM) ----
        int stride = gridDim.y * 256;
        for (int e = by * 256 + tid; e < N_EDGES; e += stride) {
            int src = ei[e], tgt = ei[N_EDGES + e];
            int pos = g_off[tgt] + atomicAdd(&g_cursor[tgt], 1);
            g_esort[pos] = src | (dre[e] << 16) | (dae[e] << 22);
        }
        return;
    }

    int row0 = by * BM;
    bool scal = (bx == 4);
    int col0 = bx * BN;

    int am = tid >> 2, ak = (tid & 3) << 2;
    int bk = tid >> 4, bc = (tid & 15) << 2;
    int tx = tid & 15, ty = tid >> 4;

    u64 acc2[4][4];  // [row-pair][col], lo=even row, hi=odd row
#pragma unroll
    for (int i = 0; i < 4; i++)
#pragma unroll
        for (int j = 0; j < 4; j++) acc2[i][j] = 0ull;

    int r0i = row0 + am, r1i = row0 + am + 64;
    bool v0 = r0i < N_NODES, v1 = r1i < N_NODES;
    float4 ra0, ra1, rb;
    const float4 z4 = make_float4(0.f, 0.f, 0.f, 0.f);

    ra0 = v0 ? *(const float4*)(inp + (size_t)r0i * 256 + ak) : z4;
    ra1 = v1 ? *(const float4*)(inp + (size_t)r1i * 256 + ak) : z4;
    if (!scal) rb = *(const float4*)(Wv + (size_t)bk * 256 + col0 + bc);
    else rb = (bc < 32) ? *(const float4*)(g_B2 + bk * 32 + bc) : z4;

    As[0][ak + 0][am] = ra0.x; As[0][ak + 1][am] = ra0.y;
    As[0][ak + 2][am] = ra0.z; As[0][ak + 3][am] = ra0.w;
    As[0][ak + 0][am + 64] = ra1.x; As[0][ak + 1][am + 64] = ra1.y;
    As[0][ak + 2][am + 64] = ra1.z; As[0][ak + 3][am + 64] = ra1.w;
    *(float4*)&Bs[0][bk][bc] = rb;
    __syncthreads();

    for (int t = 0; t < 16; t++) {
        int buf = t & 1;
        if (t < 15) {
            int k0 = (t + 1) * BK;
            ra0 = v0 ? *(const float4*)(inp + (size_t)r0i * 256 + k0 + ak) : z4;
            ra1 = v1 ? *(const float4*)(inp + (size_t)r1i * 256 + k0 + ak) : z4;
            if (!scal) rb = *(const float4*)(Wv + (size_t)(k0 + bk) * 256 + col0 + bc);
            else rb = (bc < 32) ? *(const float4*)(g_B2 + (k0 + bk) * 32 + bc) : z4;
        }
#pragma unroll
        for (int kk = 0; kk < BK; kk++) {
            const float* abase = &As[buf][kk][ty * 8];
            u64 a01 = *(const u64*)(abase + 0);
            u64 a23 = *(const u64*)(abase + 2);
            u64 a45 = *(const u64*)(abase + 4);
            u64 a67 = *(const u64*)(abase + 6);
            float4 b4 = *(const float4*)&Bs[buf][kk][tx * 4];
            u64 bb0 = bcast2(b4.x), bb1 = bcast2(b4.y), bb2 = bcast2(b4.z), bb3 = bcast2(b4.w);
            ffma2(acc2[0][0], a01, bb0); ffma2(acc2[0][1], a01, bb1);
            ffma2(acc2[0][2], a01, bb2); ffma2(acc2[0][3], a01, bb3);
            ffma2(acc2[1][0], a23, bb0); ffma2(acc2[1][1], a23, bb1);
            ffma2(acc2[1][2], a23, bb2); ffma2(acc2[1][3], a23, bb3);
            ffma2(acc2[2][0], a45, bb0); ffma2(acc2[2][1], a45, bb1);
            ffma2(acc2[2][2], a45, bb2); ffma2(acc2[2][3], a45, bb3);
            ffma2(acc2[3][0], a67, bb0); ffma2(acc2[3][1], a67, bb1);
            ffma2(acc2[3][2], a67, bb2); ffma2(acc2[3][3], a67, bb3);
        }
        if (t < 15) {
            int nb = buf ^ 1;
            As[nb][ak + 0][am] = ra0.x; As[nb][ak + 1][am] = ra0.y;
            As[nb][ak + 2][am] = ra0.z; As[nb][ak + 3][am] = ra0.w;
            As[nb][ak + 0][am + 64] = ra1.x; As[nb][ak + 1][am + 64] = ra1.y;
            As[nb][ak + 2][am + 64] = ra1.z; As[nb][ak + 3][am + 64] = ra1.w;
            *(float4*)&Bs[nb][bk][bc] = rb;
            __syncthreads();
        }
    }

    float mssrc = -1e30f, mstgt = -1e30f;
#pragma unroll
    for (int i2 = 0; i2 < 4; i2++) {
        float lo0, hi0, lo1, hi1, lo2, hi2, lo3, hi3;
        unpack2(acc2[i2][0], lo0, hi0);
        unpack2(acc2[i2][1], lo1, hi1);
        unpack2(acc2[i2][2], lo2, hi2);
        unpack2(acc2[i2][3], lo3, hi3);
        int rlo = row0 + ty * 8 + 2 * i2;
        int rhi = rlo + 1;
        if (!scal) {
            if (rlo < N_NODES)
                *(float4*)(g_value + (size_t)rlo * 256 + col0 + tx * 4) =
                    make_float4(lo0, lo1, lo2, lo3);
            if (rhi < N_NODES)
                *(float4*)(g_value + (size_t)rhi * 256 + col0 + tx * 4) =
                    make_float4(hi0, hi1, hi2, hi3);
        } else if (tx < 8) {
            if (rlo < N_NODES)
                *(float4*)(g_scal + (size_t)rlo * 32 + tx * 4) = make_float4(lo0, lo1, lo2, lo3);
            if (rhi < N_NODES)
                *(float4*)(g_scal + (size_t)rhi * 32 + tx * 4) = make_float4(hi0, hi1, hi2, hi3);
            // fold node-max: cols 0-7 = ssrc (tx 0,1), cols 8-15 = stgt (tx 2,3)
            if (tx < 2) {
                if (rlo < N_NODES) mssrc = fmaxf(mssrc, fmaxf(fmaxf(lo0, lo1), fmaxf(lo2, lo3)));
                if (rhi < N_NODES) mssrc = fmaxf(mssrc, fmaxf(fmaxf(hi0, hi1), fmaxf(hi2, hi3)));
            } else if (tx < 4) {
                if (rlo < N_NODES) mstgt = fmaxf(mstgt, fmaxf(fmaxf(lo0, lo1), fmaxf(lo2, lo3)));
                if (rhi < N_NODES) mstgt = fmaxf(mstgt, fmaxf(fmaxf(hi0, hi1), fmaxf(hi2, hi3)));
            }
        }
    }
    if (scal) {
#pragma unroll
        for (int o = 16; o; o >>= 1) {
            mssrc = fmaxf(mssrc, __shfl_xor_sync(0xFFFFFFFFu, mssrc, o));
            mstgt = fmaxf(mstgt, __shfl_xor_sync(0xFFFFFFFFu, mstgt, o));
        }
        if ((tid & 31) == 0) {
            atomicMax(&g_maxraw[0], encodef(mssrc));
            atomicMax(&g_maxraw[1], encodef(mstgt));
        }
    }
}

// ---------------- aggregation + epilogue: one WARP per node, 8 nodes per block ----------------
__global__ void __launch_bounds__(256) k_agg(const float* __restrict__ fpw,
                                             const float* __restrict__ fpb,
                                             const float* __restrict__ gateb,
                                             const float* __restrict__ fbias,
                                             float* __restrict__ out) {
    __shared__ float tdr[50 * NH];
    __shared__ float tda[4 * NH];
    __shared__ float cat_s[8][8][64];
    __shared__ float gate_s[8][8];
    int tid = threadIdx.x, lane = tid & 31, w = tid >> 5;
    for (int i = tid; i < 50 * NH; i += 256) tdr[i] = g_srel_dr[i];
    if (tid < 32) tda[tid] = g_srel_da[tid];
    __syncthreads();

    int n = blockIdx.x * 8 + w;
    float maxssrc = decodef(g_maxraw[0]);
    float maxstgt = decodef(g_maxraw[1]);
    float Mv = leaky(maxssrc + maxstgt);
    float Mr = leaky(g_tabmax[0] + g_tabmax[1] + maxstgt);

    int e0 = g_off[n], e1 = g_off[n + 1];
    float nscal = g_scal[n * 32 + lane];
    float stgt_sh = __shfl_sync(0xFFFFFFFFu, nscal, (lane & 7) + 8);

    float accv[8], accr[8];
#pragma unroll
    for (int h = 0; h < 8; h++) { accv[h] = 0.f; accr[h] = 0.f; }
    float den_l = 0.f, accq_l = 0.f;

    int soff = (lane < 8) ? lane : 16 + lane;

    int pk = (e0 < e1) ? g_esort[e0] : 0;
    for (int p = e0; p < e1; p++) {
        int pk_next = (p + 1 < e1) ? g_esort[p + 1] : 0;
        int src = pk & 0xFFFF;
        int dr = (pk >> 16) & 0x3F;
        int da = (pk >> 22) & 0x3;
        float sv = (lane < 16) ? g_scal[src * 32 + soff] : 0.f;
        float x[8];
#pragma unroll
        for (int h = 0; h < 8; h++) x[h] = g_value[(size_t)src * 256 + h * 32 + lane];
        float arg;
        if (lane < 8)
            arg = leaky(sv + stgt_sh) - Mv;
        else
            arg = leaky(tdr[dr * 8 + (lane & 7)] + tda[da * 8 + (lane & 7)] + stgt_sh) - Mr;
        float e_l = __expf(arg);
        if (lane < 16) den_l += e_l;
        if (lane >= 8 && lane < 16) accq_l += sv;
#pragma unroll
        for (int h = 0; h < 8; h++) {
            float ev = __shfl_sync(0xFFFFFFFFu, e_l, h);
            float er = __shfl_sync(0xFFFFFFFFu, e_l, 8 + h);
            accv[h] += ev * x[h];
            accr[h] += er * x[h];
        }
        pk = pk_next;
    }

    int deg = e1 - e0;
#pragma unroll
    for (int h = 0; h < 8; h++) {
        float dv = __shfl_sync(0xFFFFFFFFu, den_l, h) + EPS;
        float drr = __shfl_sync(0xFFFFFFFFu, den_l, 8 + h) + EPS;
        cat_s[w][h][lane] = accv[h] / dv;
        cat_s[w][h][32 + lane] = accr[h] / drr;
    }
    {
        float g1 = __shfl_sync(0xFFFFFFFFu, nscal, 16 + (lane & 7));
        float aq = __shfl_sync(0xFFFFFFFFu, accq_l, 8 + (lane & 7));
        if (lane < 8) {
            float nbterm = deg > 0 ? aq / (float)deg + g_cq[lane] : 0.f;
            gate_s[w][lane] = 1.f / (1.f + __expf(-(g1 + nbterm + gateb[lane])));
        }
    }
    __syncthreads();

    int h = w;
    float wreg[64];
#pragma unroll
    for (int d = 0; d < 64; d++) wreg[d] = fpw[h * 2048 + d * 32 + lane];
    float bias = fpb[h * 32 + lane];
    float fb = fbias[h * 32 + lane];
    int nbase = blockIdx.x * 8;
#pragma unroll
    for (int nn = 0; nn < 8; nn++) {
        float ho = bias;
#pragma unroll
        for (int d4 = 0; d4 < 16; d4++) {
            float4 c4 = *(const float4*)&cat_s[nn][h][d4 * 4];
            ho += c4.x * wreg[d4 * 4 + 0] + c4.y * wreg[d4 * 4 + 1] +
                  c4.z * wreg[d4 * 4 + 2] + c4.w * wreg[d4 * 4 + 3];
        }
        float gate = gate_s[nn][h];
        out[(size_t)(nbase + nn) * 256 + h * 32 + lane] = ho * gate + fb;
    }
}

// ---------------- launcher ----------------
extern "C" void kernel_launch(void* const* d_in, const int* in_sizes, int n_in,
                              void* d_out, int out_size) {
    const float* inp = (const float*)d_in[0];
    const float* Wv = (const float*)d_in[2];
    const float* Wrel = (const float*)d_in[3];
    const float* dre_emb = (const float*)d_in[4];
    const float* dae_emb = (const float*)d_in[5];
    const float* wsrc = (const float*)d_in[6];
    const float* wtgt = (const float*)d_in[7];
    const float* wrel = (const float*)d_in[8];
    const float* fpw = (const float*)d_in[9];
    const float* fpb = (const float*)d_in[10];
    const float* Wn = (const float*)d_in[11];
    const float* nbias = (const float*)d_in[12];
    const float* gatew = (const float*)d_in[13];
    const float* gateb = (const float*)d_in[14];
    const float* fbias = (const float*)d_in[15];
    const int* ei = (const int*)d_in[16];
    const int* dre = (const int*)d_in[17];
    const int* dae = (const int*)d_in[18];
    float* out = (float*)d_out;

    k_init<<<(N_NODES + 255) / 256, 256>>>();                                        // 1
    k_pre<<<882, 256>>>(Wrel, wrel, dre_emb, dae_emb, Wv, wsrc, wtgt, gatew,
                        Wn, nbias, ei);                                              // 2
    k_scan<<<1, 1024>>>();                                                           // 3
    k_gemm<<<dim3(6, (N_NODES + BM - 1) / BM), 256>>>(inp, Wv, ei, dre, dae);        // 4 (profiled)
    k_agg<<<2500, 256>>>(fpw, fpb, gateb, fbias, out);                               // 5
}

// round 6
// speedup vs baseline: 3.1751x; 1.0133x over previous
#include <cuda_runtime.h>

#define N_NODES 20000
#define N_EDGES 160000
#define NH 8
#define EPS 1e-12f
#define SLOPE 0.2f

typedef unsigned long long u64;

// ---------------- scratch ----------------
__device__ float g_value[N_NODES * 256];
__device__ float g_scal[N_NODES * 32];   // 0-7 ssrc | 8-15 stgt | 16-23 gate1 | 24-31 q
__device__ float g_B2[256 * 32];
__device__ float g_cq[NH];
__device__ float g_srel_dr[50 * NH];
__device__ float g_srel_da[4 * NH];
__device__ float g_tabmax[2];
__device__ int g_deg[N_NODES];
__device__ int g_cursor[N_NODES];
__device__ int g_off[N_NODES + 1];
__device__ int g_esort[N_EDGES];
__device__ unsigned g_maxraw[2];

__device__ __forceinline__ float leaky(float x) { return x >= 0.f ? x : SLOPE * x; }

__device__ __forceinline__ float wsum(float v) {
#pragma unroll
    for (int o = 16; o; o >>= 1) v += __shfl_xor_sync(0xFFFFFFFFu, v, o);
    return v;
}

__device__ __forceinline__ unsigned encodef(float f) {
    unsigned b = __float_as_uint(f);
    return (b & 0x80000000u) ? ~b : (b | 0x80000000u);
}
__device__ __forceinline__ float decodef(unsigned u) {
    unsigned b = (u & 0x80000000u) ? (u & 0x7FFFFFFFu) : ~u;
    return __uint_as_float(b);
}

__device__ __forceinline__ void ffma2(u64& d, u64 a, u64 b) {
    asm("fma.rn.f32x2 %0, %1, %2, %0;" : "+l"(d) : "l"(a), "l"(b));
}
__device__ __forceinline__ u64 bcast2(float x) {
    u64 r;
    unsigned u = __float_as_uint(x);
    asm("mov.b64 %0, {%1, %2};" : "=l"(r) : "r"(u), "r"(u));
    return r;
}
__device__ __forceinline__ void unpack2(u64 v, float& lo, float& hi) {
    unsigned a, b;
    asm("mov.b64 {%0, %1}, %2;" : "=r"(a), "=r"(b) : "l"(v));
    lo = __uint_as_float(a);
    hi = __uint_as_float(b);
}

// ---------------- init ----------------
__global__ void k_init() {
    int i = blockIdx.x * blockDim.x + threadIdx.x;
    if (i < N_NODES) { g_deg[i] = 0; g_cursor[i] = 0; }
    if (i < 2) g_maxraw[i] = 0u;
}

// ---------------- pre: tables(b0) | prep(b1..256) | count(b257..881) ----------------
__global__ void __launch_bounds__(256) k_pre(
    const float* __restrict__ Wrel, const float* __restrict__ wrel,
    const float* __restrict__ dre_emb, const float* __restrict__ dae_emb,
    const float* __restrict__ Wv, const float* __restrict__ wsrc,
    const float* __restrict__ wtgt, const float* __restrict__ gatew,
    const float* __restrict__ Wn, const float* __restrict__ nbias,
    const int* __restrict__ ei) {
    int b = blockIdx.x;
    int tid = threadIdx.x;
    if (b == 0) {
        __shared__ float us[NH * 128];
        __shared__ unsigned sm0, sm1;
        if (tid == 0) { sm0 = 0u; sm1 = 0u; }
        for (int id = tid; id < NH * 128; id += 256) {
            int h = id >> 7, k = id & 127;
            float s = 0.f;
#pragma unroll
            for (int j = 0; j < 16; j++) s += Wrel[k * 128 + h * 16 + j] * wrel[h * 16 + j];
            us[h * 128 + k] = s;
        }
        __syncthreads();
        float mdr = -1e30f, mda = -1e30f;
        for (int id = tid; id < 50 * NH; id += 256) {
            int r = id / NH, h = id % NH;
            float s = 0.f;
            for (int k = 0; k < 64; k++) s += dre_emb[r * 64 + k] * us[h * 128 + k];
            g_srel_dr[r * NH + h] = s;
            mdr = fmaxf(mdr, s);
        }
        for (int id = tid; id < 4 * NH; id += 256) {
            int a = id / NH, h = id % NH;
            float s = 0.f;
            for (int k = 0; k < 64; k++) s += dae_emb[a * 64 + k] * us[h * 128 + 64 + k];
            g_srel_da[a * NH + h] = s;
            mda = fmaxf(mda, s);
        }
        atomicMax(&sm0, encodef(mdr));
        atomicMax(&sm1, encodef(mda));
        __syncthreads();
        if (tid == 0) {
            g_tabmax[0] = decodef(sm0);
            g_tabmax[1] = decodef(sm1);
        }
    } else if (b <= 256) {
        int k = b - 1;
        int lane = tid & 31, h = tid >> 5;
        float v = Wv[k * 256 + h * 32 + lane];
        float s1 = wsum(v * wsrc[h * 32 + lane]);
        float s2 = wsum(v * wtgt[h * 32 + lane]);
        float s3p = 0.f;
#pragma unroll
        for (int j = 0; j < 8; j++) {
            int t = j * 32 + lane;
            s3p += Wn[k * 256 + t] * gatew[(256 + t) * 8 + h];
        }
        float s3 = wsum(s3p);
        if (lane == 0) {
            g_B2[k * 32 + h] = s1;
            g_B2[k * 32 + 8 + h] = s2;
            g_B2[k * 32 + 16 + h] = gatew[k * 8 + h];
            g_B2[k * 32 + 24 + h] = s3;
        }
        if (k == 0) {
            float cp = 0.f;
#pragma unroll
            for (int j = 0; j < 8; j++) {
                int t = j * 32 + lane;
                cp += nbias[t] * gatew[(256 + t) * 8 + h];
            }
            float c = wsum(cp);
            if (lane == 0) g_cq[h] = c;
        }
    } else {
        int e = (b - 257) * 256 + tid;
        if (e < N_EDGES) atomicAdd(&g_deg[ei[N_EDGES + e]], 1);
    }
}

// ---------------- scan ----------------
__global__ void k_scan() {
    __shared__ int wsums[32];
    __shared__ int carry_s;
    int tid = threadIdx.x, lane = tid & 31, wid = tid >> 5;
    if (tid == 0) carry_s = 0;
    __syncthreads();
    for (int base = 0; base < N_NODES; base += 1024) {
        int i = base + tid;
        int v = (i < N_NODES) ? g_deg[i] : 0;
        int x = v;
#pragma unroll
        for (int o = 1; o < 32; o <<= 1) {
            int t = __shfl_up_sync(0xFFFFFFFFu, x, o);
            if (lane >= o) x += t;
        }
        if (lane == 31) wsums[wid] = x;
        __syncthreads();
        if (wid == 0) {
            int s = wsums[lane];
#pragma unroll
            for (int o = 1; o < 32; o <<= 1) {
                int t = __shfl_up_sync(0xFFFFFFFFu, s, o);
                if (lane >= o) s += t;
            }
            wsums[lane] = s;
        }
        __syncthreads();
        int wpre = wid ? wsums[wid - 1] : 0;
        int carry = carry_s;
        if (i < N_NODES) g_off[i] = carry + wpre + x - v;
        int tot = wsums[31];
        __syncthreads();
        if (tid == 0) carry_s = carry + tot;
        __syncthreads();
    }
    if (threadIdx.x == 0) g_off[N_NODES] = carry_s;
}

// ---------------- fused GEMM: bx 0-1 value 128x128 | bx 2 scal | bx 3 fill ----------------
#define BM 128
#define BK 16
#define ASTR 132
#define BSTR 132

__global__ void __launch_bounds__(256) k_gemm(const float* __restrict__ inp,
                                              const float* __restrict__ Wv,
                                              const int* __restrict__ ei,
                                              const int* __restrict__ dre,
                                              const int* __restrict__ dae) {
    __shared__ __align__(16) float As[2][BK][ASTR];
    __shared__ __align__(16) float Bs[2][BK][BSTR];
    int tid = threadIdx.x;
    int bx = blockIdx.x, by = blockIdx.y;

    if (bx == 3) {
        // ---- CSR fill (hidden under GEMM) ----
        int stride = gridDim.y * 256;
        for (int e = by * 256 + tid; e < N_EDGES; e += stride) {
            int src = ei[e], tgt = ei[N_EDGES + e];
            int pos = g_off[tgt] + atomicAdd(&g_cursor[tgt], 1);
            g_esort[pos] = src | (dre[e] << 16) | (dae[e] << 22);
        }
        return;
    }

    int row0 = by * BM;
    int am = tid >> 2, ak = (tid & 3) << 2;
    int r0i = row0 + am, r1i = row0 + am + 64;
    bool v0 = r0i < N_NODES, v1 = r1i < N_NODES;
    const float4 z4 = make_float4(0.f, 0.f, 0.f, 0.f);
    float4 ra0, ra1;

    if (bx < 2) {
        // ================= value GEMM: 128x128 tile, 8x8 per thread =================
        int col0 = bx * 128;
        int bkr = tid >> 4, bc = (tid & 15) << 3;  // B: 2 float4/thread
        int tx = tid & 15, ty = tid >> 4;

        u64 acc2[4][8];
#pragma unroll
        for (int i = 0; i < 4; i++)
#pragma unroll
            for (int j = 0; j < 8; j++) acc2[i][j] = 0ull;

        float4 rb0, rb1;
        ra0 = v0 ? *(const float4*)(inp + (size_t)r0i * 256 + ak) : z4;
        ra1 = v1 ? *(const float4*)(inp + (size_t)r1i * 256 + ak) : z4;
        rb0 = *(const float4*)(Wv + (size_t)bkr * 256 + col0 + bc);
        rb1 = *(const float4*)(Wv + (size_t)bkr * 256 + col0 + bc + 4);

        As[0][ak + 0][am] = ra0.x; As[0][ak + 1][am] = ra0.y;
        As[0][ak + 2][am] = ra0.z; As[0][ak + 3][am] = ra0.w;
        As[0][ak + 0][am + 64] = ra1.x; As[0][ak + 1][am + 64] = ra1.y;
        As[0][ak + 2][am + 64] = ra1.z; As[0][ak + 3][am + 64] = ra1.w;
        *(float4*)&Bs[0][bkr][bc] = rb0;
        *(float4*)&Bs[0][bkr][bc + 4] = rb1;
        __syncthreads();

        for (int t = 0; t < 16; t++) {
            int buf = t & 1;
            if (t < 15) {
                int k0 = (t + 1) * BK;
                ra0 = v0 ? *(const float4*)(inp + (size_t)r0i * 256 + k0 + ak) : z4;
                ra1 = v1 ? *(const float4*)(inp + (size_t)r1i * 256 + k0 + ak) : z4;
                rb0 = *(const float4*)(Wv + (size_t)(k0 + bkr) * 256 + col0 + bc);
                rb1 = *(const float4*)(Wv + (size_t)(k0 + bkr) * 256 + col0 + bc + 4);
            }
#pragma unroll
            for (int kk = 0; kk < BK; kk++) {
                const float* ab = &As[buf][kk][ty * 8];
                ulonglong2 A0 = *(const ulonglong2*)ab;
                ulonglong2 A1 = *(const ulonglong2*)(ab + 4);
                u64 a01 = A0.x, a23 = A0.y, a45 = A1.x, a67 = A1.y;
                float4 b4l = *(const float4*)&Bs[buf][kk][tx * 8];
                float4 b4h = *(const float4*)&Bs[buf][kk][tx * 8 + 4];
                u64 bb[8];
                bb[0] = bcast2(b4l.x); bb[1] = bcast2(b4l.y);
                bb[2] = bcast2(b4l.z); bb[3] = bcast2(b4l.w);
                bb[4] = bcast2(b4h.x); bb[5] = bcast2(b4h.y);
                bb[6] = bcast2(b4h.z); bb[7] = bcast2(b4h.w);
#pragma unroll
                for (int j = 0; j < 8; j++) {
                    ffma2(acc2[0][j], a01, bb[j]);
                    ffma2(acc2[1][j], a23, bb[j]);
                    ffma2(acc2[2][j], a45, bb[j]);
                    ffma2(acc2[3][j], a67, bb[j]);
                }
            }
            if (t < 15) {
                int nb = buf ^ 1;
                As[nb][ak + 0][am] = ra0.x; As[nb][ak + 1][am] = ra0.y;
                As[nb][ak + 2][am] = ra0.z; As[nb][ak + 3][am] = ra0.w;
                As[nb][ak + 0][am + 64] = ra1.x; As[nb][ak + 1][am + 64] = ra1.y;
                As[nb][ak + 2][am + 64] = ra1.z; As[nb][ak + 3][am + 64] = ra1.w;
                *(float4*)&Bs[nb][bkr][bc] = rb0;
                *(float4*)&Bs[nb][bkr][bc + 4] = rb1;
                __syncthreads();
            }
        }

#pragma unroll
        for (int i2 = 0; i2 < 4; i2++) {
            int rlo = row0 + ty * 8 + 2 * i2;
            int rhi = rlo + 1;
            float lo[8], hi[8];
#pragma unroll
            for (int j = 0; j < 8; j++) unpack2(acc2[i2][j], lo[j], hi[j]);
            if (rlo < N_NODES) {
                *(float4*)(g_value + (size_t)rlo * 256 + col0 + tx * 8) =
                    make_float4(lo[0], lo[1], lo[2], lo[3]);
                *(float4*)(g_value + (size_t)rlo * 256 + col0 + tx * 8 + 4) =
                    make_float4(lo[4], lo[5], lo[6], lo[7]);
            }
            if (rhi < N_NODES) {
                *(float4*)(g_value + (size_t)rhi * 256 + col0 + tx * 8) =
                    make_float4(hi[0], hi[1], hi[2], hi[3]);
                *(float4*)(g_value + (size_t)rhi * 256 + col0 + tx * 8 + 4) =
                    make_float4(hi[4], hi[5], hi[6], hi[7]);
            }
        }
    } else {
        // ================= scal GEMM: 128x64 tile (32 cols used), 8x4 per thread =================
        int bkr = tid >> 4, bc = (tid & 15) << 2;
        int tx = tid & 15, ty = tid >> 4;

        u64 acc2[4][4];
#pragma unroll
        for (int i = 0; i < 4; i++)
#pragma unroll
            for (int j = 0; j < 4; j++) acc2[i][j] = 0ull;

        float4 rb;
        ra0 = v0 ? *(const float4*)(inp + (size_t)r0i * 256 + ak) : z4;
        ra1 = v1 ? *(const float4*)(inp + (size_t)r1i * 256 + ak) : z4;
        rb = (bc < 32) ? *(const float4*)(g_B2 + bkr * 32 + bc) : z4;

        As[0][ak + 0][am] = ra0.x; As[0][ak + 1][am] = ra0.y;
        As[0][ak + 2][am] = ra0.z; As[0][ak + 3][am] = ra0.w;
        As[0][ak + 0][am + 64] = ra1.x; As[0][ak + 1][am + 64] = ra1.y;
        As[0][ak + 2][am + 64] = ra1.z; As[0][ak + 3][am + 64] = ra1.w;
        *(float4*)&Bs[0][bkr][bc] = rb;
        __syncthreads();

        for (int t = 0; t < 16; t++) {
            int buf = t & 1;
            if (t < 15) {
                int k0 = (t + 1) * BK;
                ra0 = v0 ? *(const float4*)(inp + (size_t)r0i * 256 + k0 + ak) : z4;
                ra1 = v1 ? *(const float4*)(inp + (size_t)r1i * 256 + k0 + ak) : z4;
                rb = (bc < 32) ? *(const float4*)(g_B2 + (k0 + bkr) * 32 + bc) : z4;
            }
#pragma unroll
            for (int kk = 0; kk < BK; kk++) {
                const float* ab = &As[buf][kk][ty * 8];
                ulonglong2 A0 = *(const ulonglong2*)ab;
                ulonglong2 A1 = *(const ulonglong2*)(ab + 4);
                u64 a01 = A0.x, a23 = A0.y, a45 = A1.x, a67 = A1.y;
                float4 b4 = *(const float4*)&Bs[buf][kk][tx * 4];
                u64 bb0 = bcast2(b4.x), bb1 = bcast2(b4.y), bb2 = bcast2(b4.z), bb3 = bcast2(b4.w);
                ffma2(acc2[0][0], a01, bb0); ffma2(acc2[0][1], a01, bb1);
                ffma2(acc2[0][2], a01, bb2); ffma2(acc2[0][3], a01, bb3);
                ffma2(acc2[1][0], a23, bb0); ffma2(acc2[1][1], a23, bb1);
                ffma2(acc2[1][2], a23, bb2); ffma2(acc2[1][3], a23, bb3);
                ffma2(acc2[2][0], a45, bb0); ffma2(acc2[2][1], a45, bb1);
                ffma2(acc2[2][2], a45, bb2); ffma2(acc2[2][3], a45, bb3);
                ffma2(acc2[3][0], a67, bb0); ffma2(acc2[3][1], a67, bb1);
                ffma2(acc2[3][2], a67, bb2); ffma2(acc2[3][3], a67, bb3);
            }
            if (t < 15) {
                int nb = buf ^ 1;
                As[nb][ak + 0][am] = ra0.x; As[nb][ak + 1][am] = ra0.y;
                As[nb][ak + 2][am] = ra0.z; As[nb][ak + 3][am] = ra0.w;
                As[nb][ak + 0][am + 64] = ra1.x; As[nb][ak + 1][am + 64] = ra1.y;
                As[nb][ak + 2][am + 64] = ra1.z; As[nb][ak + 3][am + 64] = ra1.w;
                *(float4*)&Bs[nb][bkr][bc] = rb;
                __syncthreads();
            }
        }

        float mssrc = -1e30f, mstgt = -1e30f;
#pragma unroll
        for (int i2 = 0; i2 < 4; i2++) {
            float lo0, hi0, lo1, hi1, lo2, hi2, lo3, hi3;
            unpack2(acc2[i2][0], lo0, hi0);
            unpack2(acc2[i2][1], lo1, hi1);
            unpack2(acc2[i2][2], lo2, hi2);
            unpack2(acc2[i2][3], lo3, hi3);
            int rlo = row0 + ty * 8 + 2 * i2;
            int rhi = rlo + 1;
            if (tx < 8) {
                if (rlo < N_NODES)
                    *(float4*)(g_scal + (size_t)rlo * 32 + tx * 4) = make_float4(lo0, lo1, lo2, lo3);
                if (rhi < N_NODES)
                    *(float4*)(g_scal + (size_t)rhi * 32 + tx * 4) = make_float4(hi0, hi1, hi2, hi3);
                if (tx < 2) {
                    if (rlo < N_NODES) mssrc = fmaxf(mssrc, fmaxf(fmaxf(lo0, lo1), fmaxf(lo2, lo3)));
                    if (rhi < N_NODES) mssrc = fmaxf(mssrc, fmaxf(fmaxf(hi0, hi1), fmaxf(hi2, hi3)));
                } else if (tx < 4) {
                    if (rlo < N_NODES) mstgt = fmaxf(mstgt, fmaxf(fmaxf(lo0, lo1), fmaxf(lo2, lo3)));
                    if (rhi < N_NODES) mstgt = fmaxf(mstgt, fmaxf(fmaxf(hi0, hi1), fmaxf(hi2, hi3)));
                }
            }
        }
#pragma unroll
        for (int o = 16; o; o >>= 1) {
            mssrc = fmaxf(mssrc, __shfl_xor_sync(0xFFFFFFFFu, mssrc, o));
            mstgt = fmaxf(mstgt, __shfl_xor_sync(0xFFFFFFFFu, mstgt, o));
        }
        if ((tid & 31) == 0) {
            atomicMax(&g_maxraw[0], encodef(mssrc));
            atomicMax(&g_maxraw[1], encodef(mstgt));
        }
    }
}

// ---------------- aggregation + epilogue: warp per node; lane = (head, dv-quad) ----------------
__global__ void __launch_bounds__(256) k_agg(const float* __restrict__ fpw,
                                             const float* __restrict__ fpb,
                                             const float* __restrict__ gateb,
                                             const float* __restrict__ fbias,
                                             float* __restrict__ out) {
    __shared__ float tdr[50 * NH];
    __shared__ float tda[4 * NH];
    __shared__ float cat_s[8][8][64];
    __shared__ float gate_s[8][8];
    int tid = threadIdx.x, lane = tid & 31, w = tid >> 5;
    for (int i = tid; i < 50 * NH; i += 256) tdr[i] = g_srel_dr[i];
    if (tid < 32) tda[tid] = g_srel_da[tid];
    __syncthreads();

    int n = blockIdx.x * 8 + w;
    float maxssrc = decodef(g_maxraw[0]);
    float maxstgt = decodef(g_maxraw[1]);
    float Mv = leaky(maxssrc + maxstgt);
    float Mr = leaky(g_tabmax[0] + g_tabmax[1] + maxstgt);

    int h = lane >> 2;      // head
    int q4 = lane & 3;      // dv quad: components q4*8 .. q4*8+7
    int e0 = g_off[n], e1 = g_off[n + 1];
    float stgt = g_scal[n * 32 + 8 + h];

    float accv[8], accr[8];
#pragma unroll
    for (int j = 0; j < 8; j++) { accv[j] = 0.f; accr[j] = 0.f; }
    float denv = 0.f, denr = 0.f, accq = 0.f;

    const float* vbase = g_value + h * 32 + q4 * 8;

    int pk = (e0 < e1) ? g_esort[e0] : 0;
    for (int p = e0; p < e1; p++) {
        int pk_next = (p + 1 < e1) ? g_esort[p + 1] : 0;
        int src = pk & 0xFFFF;
        int dr = (pk >> 16) & 0x3F;
        int da = (pk >> 22) & 0x3;
        float sv = g_scal[src * 32 + h];
        float qv = g_scal[src * 32 + 24 + h];
        float4 x0 = *(const float4*)(vbase + (size_t)src * 256);
        float4 x1 = *(const float4*)(vbase + (size_t)src * 256 + 4);
        float ev = __expf(leaky(sv + stgt) - Mv);
        float er = __expf(leaky(tdr[dr * 8 + h] + tda[da * 8 + h] + stgt) - Mr);
        denv += ev;
        denr += er;
        accq += qv;
        accv[0] += ev * x0.x; accv[1] += ev * x0.y; accv[2] += ev * x0.z; accv[3] += ev * x0.w;
        accv[4] += ev * x1.x; accv[5] += ev * x1.y; accv[6] += ev * x1.z; accv[7] += ev * x1.w;
        accr[0] += er * x0.x; accr[1] += er * x0.y; accr[2] += er * x0.z; accr[3] += er * x0.w;
        accr[4] += er * x1.x; accr[5] += er * x1.y; accr[6] += er * x1.z; accr[7] += er * x1.w;
        pk = pk_next;
    }

    float idv = 1.f / (denv + EPS);
    float idr = 1.f / (denr + EPS);
    *(float4*)&cat_s[w][h][q4 * 8] =
        make_float4(accv[0] * idv, accv[1] * idv, accv[2] * idv, accv[3] * idv);
    *(float4*)&cat_s[w][h][q4 * 8 + 4] =
        make_float4(accv[4] * idv, accv[5] * idv, accv[6] * idv, accv[7] * idv);
    *(float4*)&cat_s[w][h][32 + q4 * 8] =
        make_float4(accr[0] * idr, accr[1] * idr, accr[2] * idr, accr[3] * idr);
    *(float4*)&cat_s[w][h][32 + q4 * 8 + 4] =
        make_float4(accr[4] * idr, accr[5] * idr, accr[6] * idr, accr[7] * idr);

    int deg = e1 - e0;
    if (q4 == 0) {
        float g1 = g_scal[n * 32 + 16 + h];
        float nbterm = deg > 0 ? accq / (float)deg + g_cq[h] : 0.f;
        gate_s[w][h] = 1.f / (1.f + __expf(-(g1 + nbterm + gateb[h])));
    }
    __syncthreads();

    // ---- epilogue: warp w == head h, loops over the block's 8 nodes ----
    int hh = w;
    float wreg[64];
#pragma unroll
    for (int d = 0; d < 64; d++) wreg[d] = fpw[hh * 2048 + d * 32 + lane];
    float bias = fpb[hh * 32 + lane];
    float fb = fbias[hh * 32 + lane];
    int nbase = blockIdx.x * 8;
#pragma unroll
    for (int nn = 0; nn < 8; nn++) {
        float ho = bias;
#pragma unroll
        for (int d4 = 0; d4 < 16; d4++) {
            float4 c4 = *(const float4*)&cat_s[nn][hh][d4 * 4];
            ho += c4.x * wreg[d4 * 4 + 0] + c4.y * wreg[d4 * 4 + 1] +
                  c4.z * wreg[d4 * 4 + 2] + c4.w * wreg[d4 * 4 + 3];
        }
        float gate = gate_s[nn][hh];
        out[(size_t)(nbase + nn) * 256 + hh * 32 + lane] = ho * gate + fb;
    }
}

// ---------------- launcher ----------------
extern "C" void kernel_launch(void* const* d_in, const int* in_sizes, int n_in,
                              void* d_out, int out_size) {
    const float* inp = (const float*)d_in[0];
    const float* Wv = (const float*)d_in[2];
    const float* Wrel = (const float*)d_in[3];
    const float* dre_emb = (const float*)d_in[4];
    const float* dae_emb = (const float*)d_in[5];
    const float* wsrc = (const float*)d_in[6];
    const float* wtgt = (const float*)d_in[7];
    const float* wrel = (const float*)d_in[8];
    const float* fpw = (const float*)d_in[9];
    const float* fpb = (const float*)d_in[10];
    const float* Wn = (const float*)d_in[11];
    const float* nbias = (const float*)d_in[12];
    const float* gatew = (const float*)d_in[13];
    const float* gateb = (const float*)d_in[14];
    const float* fbias = (const float*)d_in[15];
    const int* ei = (const int*)d_in[16];
    const int* dre = (const int*)d_in[17];
    const int* dae = (const int*)d_in[18];
    float* out = (float*)d_out;

    k_init<<<(N_NODES + 255) / 256, 256>>>();                                        // 1
    k_pre<<<882, 256>>>(Wrel, wrel, dre_emb, dae_emb, Wv, wsrc, wtgt, gatew,
                        Wn, nbias, ei);                                              // 2
    k_scan<<<1, 1024>>>();                                                           // 3
    k_gemm<<<dim3(4, (N_NODES + BM - 1) / BM), 256>>>(inp, Wv, ei, dre, dae);        // 4 (profiled)
    k_agg<<<2500, 256>>>(fpw, fpb, gateb, fbias, out);                               // 5
}

// round 7
// speedup vs baseline: 3.5121x; 1.1062x over previous
#include <cuda_runtime.h>

#define N_NODES 20000
#define N_EDGES 160000
#define NH 8
#define EPS 1e-12f
#define SLOPE 0.2f

typedef unsigned long long u64;

// ---------------- scratch (zero-initialized at module load; k_agg re-zeroes deg/cursor) ----------------
__device__ float g_value[N_NODES * 256];
__device__ float g_scal[N_NODES * 32];   // 0-7 ssrc | 8-15 stgt | 16-23 gate1 | 24-31 q
__device__ float g_B2[256 * 32];
__device__ float g_cq[NH];
__device__ float g_srel_dr[50 * NH];
__device__ float g_srel_da[4 * NH];
__device__ float g_tabmax[2];
__device__ int g_deg[N_NODES];
__device__ int g_cursor[N_NODES];
__device__ int g_off[N_NODES + 1];
__device__ int g_esort[N_EDGES];
__device__ unsigned g_maxraw[2];

__device__ __forceinline__ float leaky(float x) { return x >= 0.f ? x : SLOPE * x; }

__device__ __forceinline__ float wsum(float v) {
#pragma unroll
    for (int o = 16; o; o >>= 1) v += __shfl_xor_sync(0xFFFFFFFFu, v, o);
    return v;
}

__device__ __forceinline__ unsigned encodef(float f) {
    unsigned b = __float_as_uint(f);
    return (b & 0x80000000u) ? ~b : (b | 0x80000000u);
}
__device__ __forceinline__ float decodef(unsigned u) {
    unsigned b = (u & 0x80000000u) ? (u & 0x7FFFFFFFu) : ~u;
    return __uint_as_float(b);
}

__device__ __forceinline__ void ffma2(u64& d, u64 a, u64 b) {
    asm("fma.rn.f32x2 %0, %1, %2, %0;" : "+l"(d) : "l"(a), "l"(b));
}
__device__ __forceinline__ u64 bcast2(float x) {
    u64 r;
    unsigned u = __float_as_uint(x);
    asm("mov.b64 %0, {%1, %2};" : "=l"(r) : "r"(u), "r"(u));
    return r;
}
__device__ __forceinline__ void unpack2(u64 v, float& lo, float& hi) {
    unsigned a, b;
    asm("mov.b64 {%0, %1}, %2;" : "=r"(a), "=r"(b) : "l"(v));
    lo = __uint_as_float(a);
    hi = __uint_as_float(b);
}

// ---------------- pre: tables(b0) | prep(b1..256) | count(b257..881) ----------------
// g_deg/g_cursor are zero on entry: zero-init on first call, re-zeroed by k_agg's tail after.
__global__ void __launch_bounds__(256) k_pre(
    const float* __restrict__ Wrel, const float* __restrict__ wrel,
    const float* __restrict__ dre_emb, const float* __restrict__ dae_emb,
    const float* __restrict__ Wv, const float* __restrict__ wsrc,
    const float* __restrict__ wtgt, const float* __restrict__ gatew,
    const float* __restrict__ Wn, const float* __restrict__ nbias,
    const int* __restrict__ ei) {
    int b = blockIdx.x;
    int tid = threadIdx.x;
    if (b == 0) {
        __shared__ float us[NH * 128];
        __shared__ unsigned sm0, sm1;
        if (tid == 0) { sm0 = 0u; sm1 = 0u; }
        if (tid < 2) g_maxraw[tid] = 0u;  // consumed by k_gemm (runs after) and k_agg
        for (int id = tid; id < NH * 128; id += 256) {
            int h = id >> 7, k = id & 127;
            float s = 0.f;
#pragma unroll
            for (int j = 0; j < 16; j++) s += Wrel[k * 128 + h * 16 + j] * wrel[h * 16 + j];
            us[h * 128 + k] = s;
        }
        __syncthreads();
        float mdr = -1e30f, mda = -1e30f;
        for (int id = tid; id < 50 * NH; id += 256) {
            int r = id / NH, h = id % NH;
            float s = 0.f;
            for (int k = 0; k < 64; k++) s += dre_emb[r * 64 + k] * us[h * 128 + k];
            g_srel_dr[r * NH + h] = s;
            mdr = fmaxf(mdr, s);
        }
        for (int id = tid; id < 4 * NH; id += 256) {
            int a = id / NH, h = id % NH;
            float s = 0.f;
            for (int k = 0; k < 64; k++) s += dae_emb[a * 64 + k] * us[h * 128 + 64 + k];
            g_srel_da[a * NH + h] = s;
            mda = fmaxf(mda, s);
        }
        atomicMax(&sm0, encodef(mdr));
        atomicMax(&sm1, encodef(mda));
        __syncthreads();
        if (tid == 0) {
            g_tabmax[0] = decodef(sm0);
            g_tabmax[1] = decodef(sm1);
        }
    } else if (b <= 256) {
        int k = b - 1;
        int lane = tid & 31, h = tid >> 5;
        float v = Wv[k * 256 + h * 32 + lane];
        float s1 = wsum(v * wsrc[h * 32 + lane]);
        float s2 = wsum(v * wtgt[h * 32 + lane]);
        float s3p = 0.f;
#pragma unroll
        for (int j = 0; j < 8; j++) {
            int t = j * 32 + lane;
            s3p += Wn[k * 256 + t] * gatew[(256 + t) * 8 + h];
        }
        float s3 = wsum(s3p);
        if (lane == 0) {
            g_B2[k * 32 + h] = s1;
            g_B2[k * 32 + 8 + h] = s2;
            g_B2[k * 32 + 16 + h] = gatew[k * 8 + h];
            g_B2[k * 32 + 24 + h] = s3;
        }
        if (k == 0) {
            float cp = 0.f;
#pragma unroll
            for (int j = 0; j < 8; j++) {
                int t = j * 32 + lane;
                cp += nbias[t] * gatew[(256 + t) * 8 + h];
            }
            float c = wsum(cp);
            if (lane == 0) g_cq[h] = c;
        }
    } else {
        int e = (b - 257) * 256 + tid;
        if (e < N_EDGES) atomicAdd(&g_deg[ei[N_EDGES + e]], 1);
    }
}

// ---------------- scan ----------------
__global__ void k_scan() {
    __shared__ int wsums[32];
    __shared__ int carry_s;
    int tid = threadIdx.x, lane = tid & 31, wid = tid >> 5;
    if (tid == 0) carry_s = 0;
    __syncthreads();
    for (int base = 0; base < N_NODES; base += 1024) {
        int i = base + tid;
        int v = (i < N_NODES) ? g_deg[i] : 0;
        int x = v;
#pragma unroll
        for (int o = 1; o < 32; o <<= 1) {
            int t = __shfl_up_sync(0xFFFFFFFFu, x, o);
            if (lane >= o) x += t;
        }
        if (lane == 31) wsums[wid] = x;
        __syncthreads();
        if (wid == 0) {
            int s = wsums[lane];
#pragma unroll
            for (int o = 1; o < 32; o <<= 1) {
                int t = __shfl_up_sync(0xFFFFFFFFu, s, o);
                if (lane >= o) s += t;
            }
            wsums[lane] = s;
        }
        __syncthreads();
        int wpre = wid ? wsums[wid - 1] : 0;
        int carry = carry_s;
        if (i < N_NODES) g_off[i] = carry + wpre + x - v;
        int tot = wsums[31];
        __syncthreads();
        if (tid == 0) carry_s = carry + tot;
        __syncthreads();
    }
    if (threadIdx.x == 0) g_off[N_NODES] = carry_s;
}

// ---------------- fused GEMM (FFMA2, 64-wide tiles) + nodemax + CSR fill ----------------
#define BM 128
#define BN 64
#define BK 16
#define ASTR 132
#define BSTR 68

__global__ void __launch_bounds__(256) k_gemm(const float* __restrict__ inp,
                                              const float* __restrict__ Wv,
                                              const int* __restrict__ ei,
                                              const int* __restrict__ dre,
                                              const int* __restrict__ dae) {
    __shared__ float As[2][BK][ASTR];
    __shared__ float Bs[2][BK][BSTR];
    int tid = threadIdx.x;
    int bx = blockIdx.x, by = blockIdx.y;

    if (bx == 5) {
        // ---- CSR fill (hidden under GEMM) ----
        int stride = gridDim.y * 256;
        for (int e = by * 256 + tid; e < N_EDGES; e += stride) {
            int src = ei[e], tgt = ei[N_EDGES + e];
            int pos = g_off[tgt] + atomicAdd(&g_cursor[tgt], 1);
            g_esort[pos] = src | (dre[e] << 16) | (dae[e] << 22);
        }
        return;
    }

    int row0 = by * BM;
    bool scal = (bx == 4);
    int col0 = bx * BN;

    int am = tid >> 2, ak = (tid & 3) << 2;
    int bk = tid >> 4, bc = (tid & 15) << 2;
    int tx = tid & 15, ty = tid >> 4;

    u64 acc2[4][4];
#pragma unroll
    for (int i = 0; i < 4; i++)
#pragma unroll
        for (int j = 0; j < 4; j++) acc2[i][j] = 0ull;

    int r0i = row0 + am, r1i = row0 + am + 64;
    bool v0 = r0i < N_NODES, v1 = r1i < N_NODES;
    float4 ra0, ra1, rb;
    const float4 z4 = make_float4(0.f, 0.f, 0.f, 0.f);

    ra0 = v0 ? *(const float4*)(inp + (size_t)r0i * 256 + ak) : z4;
    ra1 = v1 ? *(const float4*)(inp + (size_t)r1i * 256 + ak) : z4;
    if (!scal) rb = *(const float4*)(Wv + (size_t)bk * 256 + col0 + bc);
    else rb = (bc < 32) ? *(const float4*)(g_B2 + bk * 32 + bc) : z4;

    As[0][ak + 0][am] = ra0.x; As[0][ak + 1][am] = ra0.y;
    As[0][ak + 2][am] = ra0.z; As[0][ak + 3][am] = ra0.w;
    As[0][ak + 0][am + 64] = ra1.x; As[0][ak + 1][am + 64] = ra1.y;
    As[0][ak + 2][am + 64] = ra1.z; As[0][ak + 3][am + 64] = ra1.w;
    *(float4*)&Bs[0][bk][bc] = rb;
    __syncthreads();

    for (int t = 0; t < 16; t++) {
        int buf = t & 1;
        if (t < 15) {
            int k0 = (t + 1) * BK;
            ra0 = v0 ? *(const float4*)(inp + (size_t)r0i * 256 + k0 + ak) : z4;
            ra1 = v1 ? *(const float4*)(inp + (size_t)r1i * 256 + k0 + ak) : z4;
            if (!scal) rb = *(const float4*)(Wv + (size_t)(k0 + bk) * 256 + col0 + bc);
            else rb = (bc < 32) ? *(const float4*)(g_B2 + (k0 + bk) * 32 + bc) : z4;
        }
#pragma unroll
        for (int kk = 0; kk < BK; kk++) {
            const float* abase = &As[buf][kk][ty * 8];
            u64 a01 = *(const u64*)(abase + 0);
            u64 a23 = *(const u64*)(abase + 2);
            u64 a45 = *(const u64*)(abase + 4);
            u64 a67 = *(const u64*)(abase + 6);
            float4 b4 = *(const float4*)&Bs[buf][kk][tx * 4];
            u64 bb0 = bcast2(b4.x), bb1 = bcast2(b4.y), bb2 = bcast2(b4.z), bb3 = bcast2(b4.w);
            ffma2(acc2[0][0], a01, bb0); ffma2(acc2[0][1], a01, bb1);
            ffma2(acc2[0][2], a01, bb2); ffma2(acc2[0][3], a01, bb3);
            ffma2(acc2[1][0], a23, bb0); ffma2(acc2[1][1], a23, bb1);
            ffma2(acc2[1][2], a23, bb2); ffma2(acc2[1][3], a23, bb3);
            ffma2(acc2[2][0], a45, bb0); ffma2(acc2[2][1], a45, bb1);
            ffma2(acc2[2][2], a45, bb2); ffma2(acc2[2][3], a45, bb3);
            ffma2(acc2[3][0], a67, bb0); ffma2(acc2[3][1], a67, bb1);
            ffma2(acc2[3][2], a67, bb2); ffma2(acc2[3][3], a67, bb3);
        }
        if (t < 15) {
            int nb = buf ^ 1;
            As[nb][ak + 0][am] = ra0.x; As[nb][ak + 1][am] = ra0.y;
            As[nb][ak + 2][am] = ra0.z; As[nb][ak + 3][am] = ra0.w;
            As[nb][ak + 0][am + 64] = ra1.x; As[nb][ak + 1][am + 64] = ra1.y;
            As[nb][ak + 2][am + 64] = ra1.z; As[nb][ak + 3][am + 64] = ra1.w;
            *(float4*)&Bs[nb][bk][bc] = rb;
            __syncthreads();
        }
    }

    float mssrc = -1e30f, mstgt = -1e30f;
#pragma unroll
    for (int i2 = 0; i2 < 4; i2++) {
        float lo0, hi0, lo1, hi1, lo2, hi2, lo3, hi3;
        unpack2(acc2[i2][0], lo0, hi0);
        unpack2(acc2[i2][1], lo1, hi1);
        unpack2(acc2[i2][2], lo2, hi2);
        unpack2(acc2[i2][3], lo3, hi3);
        int rlo = row0 + ty * 8 + 2 * i2;
        int rhi = rlo + 1;
        if (!scal) {
            if (rlo < N_NODES)
                *(float4*)(g_value + (size_t)rlo * 256 + col0 + tx * 4) =
                    make_float4(lo0, lo1, lo2, lo3);
            if (rhi < N_NODES)
                *(float4*)(g_value + (size_t)rhi * 256 + col0 + tx * 4) =
                    make_float4(hi0, hi1, hi2, hi3);
        } else if (tx < 8) {
            if (rlo < N_NODES)
                *(float4*)(g_scal + (size_t)rlo * 32 + tx * 4) = make_float4(lo0, lo1, lo2, lo3);
            if (rhi < N_NODES)
                *(float4*)(g_scal + (size_t)rhi * 32 + tx * 4) = make_float4(hi0, hi1, hi2, hi3);
            if (tx < 2) {
                if (rlo < N_NODES) mssrc = fmaxf(mssrc, fmaxf(fmaxf(lo0, lo1), fmaxf(lo2, lo3)));
                if (rhi < N_NODES) mssrc = fmaxf(mssrc, fmaxf(fmaxf(hi0, hi1), fmaxf(hi2, hi3)));
            } else if (tx < 4) {
                if (rlo < N_NODES) mstgt = fmaxf(mstgt, fmaxf(fmaxf(lo0, lo1), fmaxf(lo2, lo3)));
                if (rhi < N_NODES) mstgt = fmaxf(mstgt, fmaxf(fmaxf(hi0, hi1), fmaxf(hi2, hi3)));
            }
        }
    }
    if (scal) {
#pragma unroll
        for (int o = 16; o; o >>= 1) {
            mssrc = fmaxf(mssrc, __shfl_xor_sync(0xFFFFFFFFu, mssrc, o));
            mstgt = fmaxf(mstgt, __shfl_xor_sync(0xFFFFFFFFu, mstgt, o));
        }
        if ((tid & 31) == 0) {
            atomicMax(&g_maxraw[0], encodef(mssrc));
            atomicMax(&g_maxraw[1], encodef(mstgt));
        }
    }
}

// ---------------- aggregation + epilogue: warp per node; lane = (head, dv-quad) ----------------
__global__ void __launch_bounds__(256) k_agg(const float* __restrict__ fpw,
                                             const float* __restrict__ fpb,
                                             const float* __restrict__ gateb,
                                             const float* __restrict__ fbias,
                                             float* __restrict__ out) {
    __shared__ float tdr[50 * NH];
    __shared__ float tda[4 * NH];
    __shared__ float cat_s[8][8][64];
    __shared__ float gate_s[8][8];
    int tid = threadIdx.x, lane = tid & 31, w = tid >> 5;
    for (int i = tid; i < 50 * NH; i += 256) tdr[i] = g_srel_dr[i];
    if (tid < 32) tda[tid] = g_srel_da[tid];
    __syncthreads();

    int n = blockIdx.x * 8 + w;
    float maxssrc = decodef(g_maxraw[0]);
    float maxstgt = decodef(g_maxraw[1]);
    float Mv = leaky(maxssrc + maxstgt);
    float Mr = leaky(g_tabmax[0] + g_tabmax[1] + maxstgt);

    int h = lane >> 2;
    int q4 = lane & 3;
    int e0 = g_off[n], e1 = g_off[n + 1];
    float stgt = g_scal[n * 32 + 8 + h];

    float accv[8], accr[8];
#pragma unroll
    for (int j = 0; j < 8; j++) { accv[j] = 0.f; accr[j] = 0.f; }
    float denv = 0.f, denr = 0.f, accq = 0.f;

    const float* vbase = g_value + h * 32 + q4 * 8;

    int pk = (e0 < e1) ? g_esort[e0] : 0;
    for (int p = e0; p < e1; p++) {
        int pk_next = (p + 1 < e1) ? g_esort[p + 1] : 0;
        int src = pk & 0xFFFF;
        int dr = (pk >> 16) & 0x3F;
        int da = (pk >> 22) & 0x3;
        float sv = g_scal[src * 32 + h];
        float qv = g_scal[src * 32 + 24 + h];
        float4 x0 = *(const float4*)(vbase + (size_t)src * 256);
        float4 x1 = *(const float4*)(vbase + (size_t)src * 256 + 4);
        float ev = __expf(leaky(sv + stgt) - Mv);
        float er = __expf(leaky(tdr[dr * 8 + h] + tda[da * 8 + h] + stgt) - Mr);
        denv += ev;
        denr += er;
        accq += qv;
        accv[0] += ev * x0.x; accv[1] += ev * x0.y; accv[2] += ev * x0.z; accv[3] += ev * x0.w;
        accv[4] += ev * x1.x; accv[5] += ev * x1.y; accv[6] += ev * x1.z; accv[7] += ev * x1.w;
        accr[0] += er * x0.x; accr[1] += er * x0.y; accr[2] += er * x0.z; accr[3] += er * x0.w;
        accr[4] += er * x1.x; accr[5] += er * x1.y; accr[6] += er * x1.z; accr[7] += er * x1.w;
        pk = pk_next;
    }

    float idv = 1.f / (denv + EPS);
    float idr = 1.f / (denr + EPS);
    *(float4*)&cat_s[w][h][q4 * 8] =
        make_float4(accv[0] * idv, accv[1] * idv, accv[2] * idv, accv[3] * idv);
    *(float4*)&cat_s[w][h][q4 * 8 + 4] =
        make_float4(accv[4] * idv, accv[5] * idv, accv[6] * idv, accv[7] * idv);
    *(float4*)&cat_s[w][h][32 + q4 * 8] =
        make_float4(accr[0] * idr, accr[1] * idr, accr[2] * idr, accr[3] * idr);
    *(float4*)&cat_s[w][h][32 + q4 * 8 + 4] =
        make_float4(accr[4] * idr, accr[5] * idr, accr[6] * idr, accr[7] * idr);

    int deg = e1 - e0;
    if (q4 == 0) {
        float g1 = g_scal[n * 32 + 16 + h];
        float nbterm = deg > 0 ? accq / (float)deg + g_cq[h] : 0.f;
        gate_s[w][h] = 1.f / (1.f + __expf(-(g1 + nbterm + gateb[h])));
    }
    __syncthreads();

    // ---- epilogue: warp w == head h, loops over the block's 8 nodes ----
    int hh = w;
    float wreg[64];
#pragma unroll
    for (int d = 0; d < 64; d++) wreg[d] = fpw[hh * 2048 + d * 32 + lane];
    float bias = fpb[hh * 32 + lane];
    float fb = fbias[hh * 32 + lane];
    int nbase = blockIdx.x * 8;
#pragma unroll
    for (int nn = 0; nn < 8; nn++) {
        float ho = bias;
#pragma unroll
        for (int d4 = 0; d4 < 16; d4++) {
            float4 c4 = *(const float4*)&cat_s[nn][hh][d4 * 4];
            ho += c4.x * wreg[d4 * 4 + 0] + c4.y * wreg[d4 * 4 + 1] +
                  c4.z * wreg[d4 * 4 + 2] + c4.w * wreg[d4 * 4 + 3];
        }
        float gate = gate_s[nn][hh];
        out[(size_t)(nbase + nn) * 256 + hh * 32 + lane] = ho * gate + fb;
    }

    // ---- re-zero CSR state for the next call (not read by k_agg itself) ----
    if (tid < 8) {
        g_deg[nbase + tid] = 0;
        g_cursor[nbase + tid] = 0;
    }
}

// ---------------- launcher ----------------
extern "C" void kernel_launch(void* const* d_in, const int* in_sizes, int n_in,
                              void* d_out, int out_size) {
    const float* inp = (const float*)d_in[0];
    const float* Wv = (const float*)d_in[2];
    const float* Wrel = (const float*)d_in[3];
    const float* dre_emb = (const float*)d_in[4];
    const float* dae_emb = (const float*)d_in[5];
    const float* wsrc = (const float*)d_in[6];
    const float* wtgt = (const float*)d_in[7];
    const float* wrel = (const float*)d_in[8];
    const float* fpw = (const float*)d_in[9];
    const float* fpb = (const float*)d_in[10];
    const float* Wn = (const float*)d_in[11];
    const float* nbias = (const float*)d_in[12];
    const float* gatew = (const float*)d_in[13];
    const float* gateb = (const float*)d_in[14];
    const float* fbias = (const float*)d_in[15];
    const int* ei = (const int*)d_in[16];
    const int* dre = (const int*)d_in[17];
    const int* dae = (const int*)d_in[18];
    float* out = (float*)d_out;

    k_pre<<<882, 256>>>(Wrel, wrel, dre_emb, dae_emb, Wv, wsrc, wtgt, gatew,
                        Wn, nbias, ei);                                              // 1
    k_scan<<<1, 1024>>>();                                                           // 2
    k_gemm<<<dim3(6, (N_NODES + BM - 1) / BM), 256>>>(inp, Wv, ei, dre, dae);        // 3
    k_agg<<<2500, 256>>>(fpw, fpb, gateb, fbias, out);                               // 4 (profiled?)
}

// round 8
// speedup vs baseline: 3.6225x; 1.0314x over previous
#include <cuda_runtime.h>

#define N_NODES 20000
#define N_EDGES 160000
#define NH 8
#define EPS 1e-12f
#define SLOPE 0.2f

typedef unsigned long long u64;

// ---------------- scratch (zero-initialized at module load; k_agg re-zeroes deg/cursor) ----------------
__device__ float g_value[N_NODES * 256];
__device__ float g_scal[N_NODES * 32];   // 0-7 ssrc | 8-15 stgt | 16-23 gate1 | 24-31 q
__device__ float g_B2[256 * 32];
__device__ float g_cq[NH];
__device__ float g_srel_dr[50 * NH];
__device__ float g_srel_da[4 * NH];
__device__ float g_tabmax[2];
__device__ int g_deg[N_NODES];
__device__ int g_cursor[N_NODES];
__device__ int g_off[N_NODES + 1];
__device__ int g_esort[N_EDGES];
__device__ unsigned g_maxraw[2];

__device__ __forceinline__ float leaky(float x) { return x >= 0.f ? x : SLOPE * x; }

__device__ __forceinline__ float wsum(float v) {
#pragma unroll
    for (int o = 16; o; o >>= 1) v += __shfl_xor_sync(0xFFFFFFFFu, v, o);
    return v;
}

__device__ __forceinline__ unsigned encodef(float f) {
    unsigned b = __float_as_uint(f);
    return (b & 0x80000000u) ? ~b : (b | 0x80000000u);
}
__device__ __forceinline__ float decodef(unsigned u) {
    unsigned b = (u & 0x80000000u) ? (u & 0x7FFFFFFFu) : ~u;
    return __uint_as_float(b);
}

__device__ __forceinline__ void ffma2(u64& d, u64 a, u64 b) {
    asm("fma.rn.f32x2 %0, %1, %2, %0;" : "+l"(d) : "l"(a), "l"(b));
}
__device__ __forceinline__ u64 bcast2(float x) {
    u64 r;
    unsigned u = __float_as_uint(x);
    asm("mov.b64 %0, {%1, %2};" : "=l"(r) : "r"(u), "r"(u));
    return r;
}
__device__ __forceinline__ void unpack2(u64 v, float& lo, float& hi) {
    unsigned a, b;
    asm("mov.b64 {%0, %1}, %2;" : "=r"(a), "=r"(b) : "l"(v));
    lo = __uint_as_float(a);
    hi = __uint_as_float(b);
}

// ---------------- pre: tables(b0) | prep(b1..256) | count(b257..881) ----------------
__global__ void __launch_bounds__(256) k_pre(
    const float* __restrict__ Wrel, const float* __restrict__ wrel,
    const float* __restrict__ dre_emb, const float* __restrict__ dae_emb,
    const float* __restrict__ Wv, const float* __restrict__ wsrc,
    const float* __restrict__ wtgt, const float* __restrict__ gatew,
    const float* __restrict__ Wn, const float* __restrict__ nbias,
    const int* __restrict__ ei) {
    int b = blockIdx.x;
    int tid = threadIdx.x;
    if (b == 0) {
        __shared__ float us[NH * 128];
        __shared__ unsigned sm0, sm1;
        if (tid == 0) { sm0 = 0u; sm1 = 0u; }
        if (tid < 2) g_maxraw[tid] = 0u;
        for (int id = tid; id < NH * 128; id += 256) {
            int h = id >> 7, k = id & 127;
            float s = 0.f;
#pragma unroll
            for (int j = 0; j < 16; j++) s += Wrel[k * 128 + h * 16 + j] * wrel[h * 16 + j];
            us[h * 128 + k] = s;
        }
        __syncthreads();
        float mdr = -1e30f, mda = -1e30f;
        for (int id = tid; id < 50 * NH; id += 256) {
            int r = id / NH, h = id % NH;
            float s = 0.f;
            for (int k = 0; k < 64; k++) s += dre_emb[r * 64 + k] * us[h * 128 + k];
            g_srel_dr[r * NH + h] = s;
            mdr = fmaxf(mdr, s);
        }
        for (int id = tid; id < 4 * NH; id += 256) {
            int a = id / NH, h = id % NH;
            float s = 0.f;
            for (int k = 0; k < 64; k++) s += dae_emb[a * 64 + k] * us[h * 128 + 64 + k];
            g_srel_da[a * NH + h] = s;
            mda = fmaxf(mda, s);
        }
        atomicMax(&sm0, encodef(mdr));
        atomicMax(&sm1, encodef(mda));
        __syncthreads();
        if (tid == 0) {
            g_tabmax[0] = decodef(sm0);
            g_tabmax[1] = decodef(sm1);
        }
    } else if (b <= 256) {
        int k = b - 1;
        int lane = tid & 31, h = tid >> 5;
        float v = Wv[k * 256 + h * 32 + lane];
        float s1 = wsum(v * wsrc[h * 32 + lane]);
        float s2 = wsum(v * wtgt[h * 32 + lane]);
        float s3p = 0.f;
#pragma unroll
        for (int j = 0; j < 8; j++) {
            int t = j * 32 + lane;
            s3p += Wn[k * 256 + t] * gatew[(256 + t) * 8 + h];
        }
        float s3 = wsum(s3p);
        if (lane == 0) {
            g_B2[k * 32 + h] = s1;
            g_B2[k * 32 + 8 + h] = s2;
            g_B2[k * 32 + 16 + h] = gatew[k * 8 + h];
            g_B2[k * 32 + 24 + h] = s3;
        }
        if (k == 0) {
            float cp = 0.f;
#pragma unroll
            for (int j = 0; j < 8; j++) {
                int t = j * 32 + lane;
                cp += nbias[t] * gatew[(256 + t) * 8 + h];
            }
            float c = wsum(cp);
            if (lane == 0) g_cq[h] = c;
        }
    } else {
        int e = (b - 257) * 256 + tid;
        if (e < N_EDGES) atomicAdd(&g_deg[ei[N_EDGES + e]], 1);
    }
}

// ---------------- scan ----------------
__global__ void k_scan() {
    __shared__ int wsums[32];
    __shared__ int carry_s;
    int tid = threadIdx.x, lane = tid & 31, wid = tid >> 5;
    if (tid == 0) carry_s = 0;
    __syncthreads();
    for (int base = 0; base < N_NODES; base += 1024) {
        int i = base + tid;
        int v = (i < N_NODES) ? g_deg[i] : 0;
        int x = v;
#pragma unroll
        for (int o = 1; o < 32; o <<= 1) {
            int t = __shfl_up_sync(0xFFFFFFFFu, x, o);
            if (lane >= o) x += t;
        }
        if (lane == 31) wsums[wid] = x;
        __syncthreads();
        if (wid == 0) {
            int s = wsums[lane];
#pragma unroll
            for (int o = 1; o < 32; o <<= 1) {
                int t = __shfl_up_sync(0xFFFFFFFFu, s, o);
                if (lane >= o) s += t;
            }
            wsums[lane] = s;
        }
        __syncthreads();
        int wpre = wid ? wsums[wid - 1] : 0;
        int carry = carry_s;
        if (i < N_NODES) g_off[i] = carry + wpre + x - v;
        int tot = wsums[31];
        __syncthreads();
        if (tid == 0) carry_s = carry + tot;
        __syncthreads();
    }
    if (threadIdx.x == 0) g_off[N_NODES] = carry_s;
}

// ---------------- fused GEMM (FFMA2, 64-wide tiles) + nodemax + CSR fill ----------------
#define BM 128
#define BN 64
#define BK 16
#define ASTR 132
#define BSTR 68

__global__ void __launch_bounds__(256) k_gemm(const float* __restrict__ inp,
                                              const float* __restrict__ Wv,
                                              const int* __restrict__ ei,
                                              const int* __restrict__ dre,
                                              const int* __restrict__ dae) {
    __shared__ float As[2][BK][ASTR];
    __shared__ float Bs[2][BK][BSTR];
    int tid = threadIdx.x;
    int bx = blockIdx.x, by = blockIdx.y;

    if (bx == 5) {
        int stride = gridDim.y * 256;
        for (int e = by * 256 + tid; e < N_EDGES; e += stride) {
            int src = ei[e], tgt = ei[N_EDGES + e];
            int pos = g_off[tgt] + atomicAdd(&g_cursor[tgt], 1);
            g_esort[pos] = src | (dre[e] << 16) | (dae[e] << 22);
        }
        return;
    }

    int row0 = by * BM;
    bool scal = (bx == 4);
    int col0 = bx * BN;

    int am = tid >> 2, ak = (tid & 3) << 2;
    int bk = tid >> 4, bc = (tid & 15) << 2;
    int tx = tid & 15, ty = tid >> 4;

    u64 acc2[4][4];
#pragma unroll
    for (int i = 0; i < 4; i++)
#pragma unroll
        for (int j = 0; j < 4; j++) acc2[i][j] = 0ull;

    int r0i = row0 + am, r1i = row0 + am + 64;
    bool v0 = r0i < N_NODES, v1 = r1i < N_NODES;
    float4 ra0, ra1, rb;
    const float4 z4 = make_float4(0.f, 0.f, 0.f, 0.f);

    ra0 = v0 ? *(const float4*)(inp + (size_t)r0i * 256 + ak) : z4;
    ra1 = v1 ? *(const float4*)(inp + (size_t)r1i * 256 + ak) : z4;
    if (!scal) rb = *(const float4*)(Wv + (size_t)bk * 256 + col0 + bc);
    else rb = (bc < 32) ? *(const float4*)(g_B2 + bk * 32 + bc) : z4;

    As[0][ak + 0][am] = ra0.x; As[0][ak + 1][am] = ra0.y;
    As[0][ak + 2][am] = ra0.z; As[0][ak + 3][am] = ra0.w;
    As[0][ak + 0][am + 64] = ra1.x; As[0][ak + 1][am + 64] = ra1.y;
    As[0][ak + 2][am + 64] = ra1.z; As[0][ak + 3][am + 64] = ra1.w;
    *(float4*)&Bs[0][bk][bc] = rb;
    __syncthreads();

    for (int t = 0; t < 16; t++) {
        int buf = t & 1;
        if (t < 15) {
            int k0 = (t + 1) * BK;
            ra0 = v0 ? *(const float4*)(inp + (size_t)r0i * 256 + k0 + ak) : z4;
            ra1 = v1 ? *(const float4*)(inp + (size_t)r1i * 256 + k0 + ak) : z4;
            if (!scal) rb = *(const float4*)(Wv + (size_t)(k0 + bk) * 256 + col0 + bc);
            else rb = (bc < 32) ? *(const float4*)(g_B2 + (k0 + bk) * 32 + bc) : z4;
        }
#pragma unroll
        for (int kk = 0; kk < BK; kk++) {
            const float* abase = &As[buf][kk][ty * 8];
            u64 a01 = *(const u64*)(abase + 0);
            u64 a23 = *(const u64*)(abase + 2);
            u64 a45 = *(const u64*)(abase + 4);
            u64 a67 = *(const u64*)(abase + 6);
            float4 b4 = *(const float4*)&Bs[buf][kk][tx * 4];
            u64 bb0 = bcast2(b4.x), bb1 = bcast2(b4.y), bb2 = bcast2(b4.z), bb3 = bcast2(b4.w);
            ffma2(acc2[0][0], a01, bb0); ffma2(acc2[0][1], a01, bb1);
            ffma2(acc2[0][2], a01, bb2); ffma2(acc2[0][3], a01, bb3);
            ffma2(acc2[1][0], a23, bb0); ffma2(acc2[1][1], a23, bb1);
            ffma2(acc2[1][2], a23, bb2); ffma2(acc2[1][3], a23, bb3);
            ffma2(acc2[2][0], a45, bb0); ffma2(acc2[2][1], a45, bb1);
            ffma2(acc2[2][2], a45, bb2); ffma2(acc2[2][3], a45, bb3);
            ffma2(acc2[3][0], a67, bb0); ffma2(acc2[3][1], a67, bb1);
            ffma2(acc2[3][2], a67, bb2); ffma2(acc2[3][3], a67, bb3);
        }
        if (t < 15) {
            int nb = buf ^ 1;
            As[nb][ak + 0][am] = ra0.x; As[nb][ak + 1][am] = ra0.y;
            As[nb][ak + 2][am] = ra0.z; As[nb][ak + 3][am] = ra0.w;
            As[nb][ak + 0][am + 64] = ra1.x; As[nb][ak + 1][am + 64] = ra1.y;
            As[nb][ak + 2][am + 64] = ra1.z; As[nb][ak + 3][am + 64] = ra1.w;
            *(float4*)&Bs[nb][bk][bc] = rb;
            __syncthreads();
        }
    }

    float mssrc = -1e30f, mstgt = -1e30f;
#pragma unroll
    for (int i2 = 0; i2 < 4; i2++) {
        float lo0, hi0, lo1, hi1, lo2, hi2, lo3, hi3;
        unpack2(acc2[i2][0], lo0, hi0);
        unpack2(acc2[i2][1], lo1, hi1);
        unpack2(acc2[i2][2], lo2, hi2);
        unpack2(acc2[i2][3], lo3, hi3);
        int rlo = row0 + ty * 8 + 2 * i2;
        int rhi = rlo + 1;
        if (!scal) {
            if (rlo < N_NODES)
                *(float4*)(g_value + (size_t)rlo * 256 + col0 + tx * 4) =
                    make_float4(lo0, lo1, lo2, lo3);
            if (rhi < N_NODES)
                *(float4*)(g_value + (size_t)rhi * 256 + col0 + tx * 4) =
                    make_float4(hi0, hi1, hi2, hi3);
        } else if (tx < 8) {
            if (rlo < N_NODES)
                *(float4*)(g_scal + (size_t)rlo * 32 + tx * 4) = make_float4(lo0, lo1, lo2, lo3);
            if (rhi < N_NODES)
                *(float4*)(g_scal + (size_t)rhi * 32 + tx * 4) = make_float4(hi0, hi1, hi2, hi3);
            if (tx < 2) {
                if (rlo < N_NODES) mssrc = fmaxf(mssrc, fmaxf(fmaxf(lo0, lo1), fmaxf(lo2, lo3)));
                if (rhi < N_NODES) mssrc = fmaxf(mssrc, fmaxf(fmaxf(hi0, hi1), fmaxf(hi2, hi3)));
            } else if (tx < 4) {
                if (rlo < N_NODES) mstgt = fmaxf(mstgt, fmaxf(fmaxf(lo0, lo1), fmaxf(lo2, lo3)));
                if (rhi < N_NODES) mstgt = fmaxf(mstgt, fmaxf(fmaxf(hi0, hi1), fmaxf(hi2, hi3)));
            }
        }
    }
    if (scal) {
#pragma unroll
        for (int o = 16; o; o >>= 1) {
            mssrc = fmaxf(mssrc, __shfl_xor_sync(0xFFFFFFFFu, mssrc, o));
            mstgt = fmaxf(mstgt, __shfl_xor_sync(0xFFFFFFFFu, mstgt, o));
        }
        if ((tid & 31) == 0) {
            atomicMax(&g_maxraw[0], encodef(mssrc));
            atomicMax(&g_maxraw[1], encodef(mstgt));
        }
    }
}

// ---------------- aggregation + epilogue: warp/node; FFMA2 + pipelined loads, low regs ----------------
__global__ void __launch_bounds__(256, 3) k_agg(const float* __restrict__ fpw,
                                                const float* __restrict__ fpb,
                                                const float* __restrict__ gateb,
                                                const float* __restrict__ fbias,
                                                float* __restrict__ out) {
    __shared__ float tdr[50 * NH];
    __shared__ float tda[4 * NH];
    __shared__ float cat_s[8][8][64];
    __shared__ float gate_s[8][8];
    int tid = threadIdx.x, lane = tid & 31, w = tid >> 5;
    for (int i = tid; i < 50 * NH; i += 256) tdr[i] = g_srel_dr[i];
    if (tid < 32) tda[tid] = g_srel_da[tid];
    __syncthreads();

    int n = blockIdx.x * 8 + w;
    float maxssrc = decodef(g_maxraw[0]);
    float maxstgt = decodef(g_maxraw[1]);
    float Mv = leaky(maxssrc + maxstgt);
    float Mr = leaky(g_tabmax[0] + g_tabmax[1] + maxstgt);

    int h = lane >> 2;
    int q4 = lane & 3;
    int e0 = g_off[n], e1 = g_off[n + 1];
    float stgt = g_scal[n * 32 + 8 + h];

    u64 accv2[4], accr2[4];
#pragma unroll
    for (int j = 0; j < 4; j++) { accv2[j] = 0ull; accr2[j] = 0ull; }
    float denv = 0.f, denr = 0.f, accq = 0.f;

    const float* vbase = g_value + h * 32 + q4 * 8;

    // software pipeline: loads for iteration p issued one iteration early
    int pk = 0;
    float sv = 0.f, qv = 0.f;
    ulonglong2 X0, X1;
    if (e0 < e1) {
        pk = g_esort[e0];
        int src = pk & 0xFFFF;
        sv = g_scal[src * 32 + h];
        qv = g_scal[src * 32 + 24 + h];
        X0 = *(const ulonglong2*)(vbase + (size_t)src * 256);
        X1 = *(const ulonglong2*)(vbase + (size_t)src * 256 + 4);
    }
    for (int p = e0; p < e1; p++) {
        // prefetch next
        int pkn = (p + 1 < e1) ? g_esort[p + 1] : pk;
        int srcn = pkn & 0xFFFF;
        float svn = g_scal[srcn * 32 + h];
        float qvn = g_scal[srcn * 32 + 24 + h];
        ulonglong2 X0n = *(const ulonglong2*)(vbase + (size_t)srcn * 256);
        ulonglong2 X1n = *(const ulonglong2*)(vbase + (size_t)srcn * 256 + 4);

        // compute current
        int dr = (pk >> 16) & 0x3F;
        int da = (pk >> 22) & 0x3;
        float ev = __expf(leaky(sv + stgt) - Mv);
        float er = __expf(leaky(tdr[dr * 8 + h] + tda[da * 8 + h] + stgt) - Mr);
        denv += ev;
        denr += er;
        accq += qv;
        u64 ev2 = bcast2(ev), er2 = bcast2(er);
        ffma2(accv2[0], X0.x, ev2); ffma2(accv2[1], X0.y, ev2);
        ffma2(accv2[2], X1.x, ev2); ffma2(accv2[3], X1.y, ev2);
        ffma2(accr2[0], X0.x, er2); ffma2(accr2[1], X0.y, er2);
        ffma2(accr2[2], X1.x, er2); ffma2(accr2[3], X1.y, er2);

        pk = pkn; sv = svn; qv = qvn; X0 = X0n; X1 = X1n;
    }

    float idv = 1.f / (denv + EPS);
    float idr = 1.f / (denr + EPS);
    {
        float f0, f1, f2, f3, f4, f5, f6, f7;
        unpack2(accv2[0], f0, f1); unpack2(accv2[1], f2, f3);
        unpack2(accv2[2], f4, f5); unpack2(accv2[3], f6, f7);
        *(float4*)&cat_s[w][h][q4 * 8] = make_float4(f0 * idv, f1 * idv, f2 * idv, f3 * idv);
        *(float4*)&cat_s[w][h][q4 * 8 + 4] = make_float4(f4 * idv, f5 * idv, f6 * idv, f7 * idv);
        unpack2(accr2[0], f0, f1); unpack2(accr2[1], f2, f3);
        unpack2(accr2[2], f4, f5); unpack2(accr2[3], f6, f7);
        *(float4*)&cat_s[w][h][32 + q4 * 8] = make_float4(f0 * idr, f1 * idr, f2 * idr, f3 * idr);
        *(float4*)&cat_s[w][h][32 + q4 * 8 + 4] = make_float4(f4 * idr, f5 * idr, f6 * idr, f7 * idr);
    }

    int deg = e1 - e0;
    if (q4 == 0) {
        float g1 = g_scal[n * 32 + 16 + h];
        float nbterm = deg > 0 ? accq / (float)deg + g_cq[h] : 0.f;
        gate_s[w][h] = 1.f / (1.f + __expf(-(g1 + nbterm + gateb[h])));
    }
    __syncthreads();

    // ---- epilogue: warp w == head hh; two half-passes over d keep regs low ----
    int hh = w;
    float ho[8];
    float bias = fpb[hh * 32 + lane];
#pragma unroll
    for (int nn = 0; nn < 8; nn++) ho[nn] = bias;
#pragma unroll
    for (int half = 0; half < 2; half++) {
        float wreg[32];
#pragma unroll
        for (int d = 0; d < 32; d++) wreg[d] = fpw[hh * 2048 + (half * 32 + d) * 32 + lane];
#pragma unroll
        for (int nn = 0; nn < 8; nn++) {
            float s = 0.f;
#pragma unroll
            for (int d4 = 0; d4 < 8; d4++) {
                float4 c4 = *(const float4*)&cat_s[nn][hh][half * 32 + d4 * 4];
                s += c4.x * wreg[d4 * 4 + 0] + c4.y * wreg[d4 * 4 + 1] +
                     c4.z * wreg[d4 * 4 + 2] + c4.w * wreg[d4 * 4 + 3];
            }
            ho[nn] += s;
        }
    }
    float fb = fbias[hh * 32 + lane];
    int nbase = blockIdx.x * 8;
#pragma unroll
    for (int nn = 0; nn < 8; nn++) {
        out[(size_t)(nbase + nn) * 256 + hh * 32 + lane] = ho[nn] * gate_s[nn][hh] + fb;
    }

    // ---- re-zero CSR state for the next call ----
    if (tid < 8) {
        g_deg[nbase + tid] = 0;
        g_cursor[nbase + tid] = 0;
    }
}

// ---------------- launcher ----------------
extern "C" void kernel_launch(void* const* d_in, const int* in_sizes, int n_in,
                              void* d_out, int out_size) {
    const float* inp = (const float*)d_in[0];
    const float* Wv = (const float*)d_in[2];
    const float* Wrel = (const float*)d_in[3];
    const float* dre_emb = (const float*)d_in[4];
    const float* dae_emb = (const float*)d_in[5];
    const float* wsrc = (const float*)d_in[6];
    const float* wtgt = (const float*)d_in[7];
    const float* wrel = (const float*)d_in[8];
    const float* fpw = (const float*)d_in[9];
    const float* fpb = (const float*)d_in[10];
    const float* Wn = (const float*)d_in[11];
    const float* nbias = (const float*)d_in[12];
    const float* gatew = (const float*)d_in[13];
    const float* gateb = (const float*)d_in[14];
    const float* fbias = (const float*)d_in[15];
    const int* ei = (const int*)d_in[16];
    const int* dre = (const int*)d_in[17];
    const int* dae = (const int*)d_in[18];
    float* out = (float*)d_out;

    k_pre<<<882, 256>>>(Wrel, wrel, dre_emb, dae_emb, Wv, wsrc, wtgt, gatew,
                        Wn, nbias, ei);                                              // 1
    k_scan<<<1, 1024>>>();                                                           // 2
    k_gemm<<<dim3(6, (N_NODES + BM - 1) / BM), 256>>>(inp, Wv, ei, dre, dae);        // 3
    k_agg<<<2500, 256>>>(fpw, fpb, gateb, fbias, out);                               // 4 (profiled)
}